// round 4
// baseline (speedup 1.0000x reference)
#include <cuda_runtime.h>
#include <math.h>

// ---------------- problem constants ----------------
#define BATCH 1024
#define NT    8192
#define NS    8192
#define DIM   1024
#define NC    10
#define TEMP  100.0f

// ---------------- scratch (device globals; no allocation) ----------------
__device__ float g_logits[(size_t)BATCH * NT];   // 32 MB, reused for both softmax stages
__device__ float g_xsrc[BATCH * DIM];            // 4 MB
__device__ float g_tn[NT];
__device__ float g_sn[NS];
__device__ float g_xn[BATCH];
__device__ float g_xsn[BATCH];
__device__ float g_t[BATCH * NC];                // preds @ L

// ---------------- row squared-norms ----------------
__global__ void rownorm_kernel(const float* __restrict__ X, float* __restrict__ out, int K) {
    int row = blockIdx.x;
    const float* xr = X + (size_t)row * K;
    float s = 0.f;
    for (int k = threadIdx.x * 4; k < K; k += blockDim.x * 4) {
        float4 v = *reinterpret_cast<const float4*>(xr + k);
        s += v.x * v.x + v.y * v.y + v.z * v.z + v.w * v.w;
    }
    #pragma unroll
    for (int o = 16; o > 0; o >>= 1) s += __shfl_xor_sync(0xffffffffu, s, o);
    __shared__ float ws[8];
    int wid = threadIdx.x >> 5, lid = threadIdx.x & 31;
    if (lid == 0) ws[wid] = s;
    __syncthreads();
    if (threadIdx.x == 0) {
        float t = 0.f;
        for (int i = 0; i < (int)(blockDim.x >> 5); i++) t += ws[i];
        out[row] = t;
    }
}

// ---------------- SGEMM (fp32, single-buffer smem), templated epilogue ----------------
// A: [M,K] row-major.  B: BT ? [N,K] : [K,N] row-major.
// MODE 0: C = A*B          (plain)
// MODE 1: C = -T*sqrt(max(rnA[m]+rnB[n]-2*acc, 1e-12))
// MODE 2: C = -T*(sqrt(...) + sum_c Tm[m,c]*SHL[n,c])
template<int BM, int BN, int BK, int TM, int TN, bool BT, int MODE>
__global__ void __launch_bounds__((BM / TM) * (BN / TN))
gemm_kernel(const float* __restrict__ A, const float* __restrict__ B,
            float* __restrict__ C, int M, int N, int K,
            const float* __restrict__ rnA, const float* __restrict__ rnB,
            const float* __restrict__ Tm, const float* __restrict__ SHL)
{
    constexpr int THREADS = (BM / TM) * (BN / TN);
    constexpr int PAD = 4;
    __shared__ float As[BK][BM + PAD];
    __shared__ float Bs[BK][BN + PAD];

    const int tid = threadIdx.x;
    const int tx = tid % (BN / TN);
    const int ty = tid / (BN / TN);
    const int row0 = blockIdx.y * BM;
    const int col0 = blockIdx.x * BN;

    float acc[TM][TN];
    #pragma unroll
    for (int i = 0; i < TM; i++)
        #pragma unroll
        for (int j = 0; j < TN; j++) acc[i][j] = 0.f;

    // A tile load mapping: float4 along K
    constexpr int AK4 = BK / 4;
    const int a_r = tid / AK4;
    const int a_c = (tid % AK4) * 4;
    constexpr int A_IT = THREADS / AK4;

    // B tile load mappings
    constexpr int BK4 = BK / 4;       // for BT (B is [N,K])
    const int bt_r = tid / BK4;
    const int bt_c = (tid % BK4) * 4;
    constexpr int BT_IT = THREADS / BK4;

    constexpr int BN4 = BN / 4;       // for !BT (B is [K,N])
    const int bn_r = tid / BN4;
    const int bn_c = (tid % BN4) * 4;
    constexpr int BNR_IT = THREADS / BN4;

    for (int k0 = 0; k0 < K; k0 += BK) {
        // load A tile (transpose into As[k][m])
        #pragma unroll
        for (int it = 0; it < BM / A_IT; it++) {
            int r = a_r + it * A_IT;
            float4 v = *reinterpret_cast<const float4*>(A + (size_t)(row0 + r) * K + (k0 + a_c));
            As[a_c + 0][r] = v.x; As[a_c + 1][r] = v.y;
            As[a_c + 2][r] = v.z; As[a_c + 3][r] = v.w;
        }
        if (BT) {
            #pragma unroll
            for (int it = 0; it < BN / BT_IT; it++) {
                int r = bt_r + it * BT_IT;
                float4 v = *reinterpret_cast<const float4*>(B + (size_t)(col0 + r) * K + (k0 + bt_c));
                Bs[bt_c + 0][r] = v.x; Bs[bt_c + 1][r] = v.y;
                Bs[bt_c + 2][r] = v.z; Bs[bt_c + 3][r] = v.w;
            }
        } else {
            #pragma unroll
            for (int it = 0; it < BK / BNR_IT; it++) {
                int r = bn_r + it * BNR_IT;
                float4 v = *reinterpret_cast<const float4*>(B + (size_t)(k0 + r) * N + (col0 + bn_c));
                *reinterpret_cast<float4*>(&Bs[r][bn_c]) = v;
            }
        }
        __syncthreads();
        #pragma unroll
        for (int kk = 0; kk < BK; kk++) {
            float af[TM], bf[TN];
            #pragma unroll
            for (int i = 0; i < TM; i += 4)
                *reinterpret_cast<float4*>(&af[i]) =
                    *reinterpret_cast<const float4*>(&As[kk][ty * TM + i]);
            #pragma unroll
            for (int j = 0; j < TN; j += 4)
                *reinterpret_cast<float4*>(&bf[j]) =
                    *reinterpret_cast<const float4*>(&Bs[kk][tx * TN + j]);
            #pragma unroll
            for (int i = 0; i < TM; i++)
                #pragma unroll
                for (int j = 0; j < TN; j++)
                    acc[i][j] = fmaf(af[i], bf[j], acc[i][j]);
        }
        __syncthreads();
    }

    // ---------------- epilogue ----------------
    if (MODE == 0) {
        #pragma unroll
        for (int i = 0; i < TM; i++) {
            int gm = row0 + ty * TM + i;
            #pragma unroll
            for (int j = 0; j < TN; j += 4) {
                float4 v = make_float4(acc[i][j], acc[i][j + 1], acc[i][j + 2], acc[i][j + 3]);
                *reinterpret_cast<float4*>(&C[(size_t)gm * N + (col0 + tx * TN + j)]) = v;
            }
        }
    } else {
        float ra[TM];
        #pragma unroll
        for (int i = 0; i < TM; i++) ra[i] = __ldg(&rnA[row0 + ty * TM + i]);
        #pragma unroll
        for (int j = 0; j < TN; j++) {
            int gn = col0 + tx * TN + j;
            float rb = __ldg(&rnB[gn]);
            float sv[NC];
            if (MODE == 2) {
                #pragma unroll
                for (int c = 0; c < NC; c++) sv[c] = __ldg(&SHL[(size_t)gn * NC + c]);
            }
            #pragma unroll
            for (int i = 0; i < TM; i++) {
                int gm = row0 + ty * TM + i;
                float sq = ra[i] + rb - 2.f * acc[i][j];
                float d = sqrtf(fmaxf(sq, 1e-12f));
                if (MODE == 2) {
                    float lab = 0.f;
                    #pragma unroll
                    for (int c = 0; c < NC; c++)
                        lab = fmaf(__ldg(&Tm[gm * NC + c]), sv[c], lab);
                    d += lab;
                }
                C[(size_t)gm * N + gn] = -TEMP * d;
            }
        }
    }
}

// ---------------- in-place row softmax (rows of length NCOL) ----------------
template<int NCOL, int THREADS>
__global__ void softmax_rows_kernel(float* __restrict__ X) {
    constexpr int PER = NCOL / THREADS;
    int row = blockIdx.x;
    float* xr = X + (size_t)row * NCOL;
    int tid = threadIdx.x;
    float r[PER];
    float mx = -INFINITY;
    #pragma unroll
    for (int i = 0; i < PER; i++) {
        r[i] = xr[tid + i * THREADS];
        mx = fmaxf(mx, r[i]);
    }
    __shared__ float sred[THREADS / 32];
    // block max
    #pragma unroll
    for (int o = 16; o > 0; o >>= 1) mx = fmaxf(mx, __shfl_xor_sync(0xffffffffu, mx, o));
    if ((tid & 31) == 0) sred[tid >> 5] = mx;
    __syncthreads();
    {
        float m = sred[0];
        #pragma unroll
        for (int i = 1; i < THREADS / 32; i++) m = fmaxf(m, sred[i]);
        mx = m;
    }
    __syncthreads();
    float s = 0.f;
    #pragma unroll
    for (int i = 0; i < PER; i++) {
        r[i] = expf(r[i] - mx);
        s += r[i];
    }
    #pragma unroll
    for (int o = 16; o > 0; o >>= 1) s += __shfl_xor_sync(0xffffffffu, s, o);
    if ((tid & 31) == 0) sred[tid >> 5] = s;
    __syncthreads();
    {
        float m = 0.f;
        #pragma unroll
        for (int i = 0; i < THREADS / 32; i++) m += sred[i];
        s = m;
    }
    float inv = 1.f / s;
    #pragma unroll
    for (int i = 0; i < PER; i++) xr[tid + i * THREADS] = r[i] * inv;
}

// ---------------- classifier head: preds = softmax(xsrc@W+b); t = preds@L; xsn ----------------
__global__ void preds_kernel(const float* __restrict__ xsrc, const float* __restrict__ W,
                             const float* __restrict__ b, const float* __restrict__ L,
                             float* __restrict__ t_out, float* __restrict__ xsn)
{
    int row = blockIdx.x;
    int tid = threadIdx.x;
    const float* xr = xsrc + (size_t)row * DIM;
    float acc[NC];
    #pragma unroll
    for (int c = 0; c < NC; c++) acc[c] = 0.f;
    float nrm = 0.f;
    for (int k = tid; k < DIM; k += blockDim.x) {
        float xv = xr[k];
        nrm = fmaf(xv, xv, nrm);
        #pragma unroll
        for (int c = 0; c < NC; c++) acc[c] = fmaf(xv, __ldg(&W[k * NC + c]), acc[c]);
    }
    __shared__ float red[NC + 1][128];
    #pragma unroll
    for (int c = 0; c < NC; c++) red[c][tid] = acc[c];
    red[NC][tid] = nrm;
    __syncthreads();
    for (int st = 64; st > 0; st >>= 1) {
        if (tid < st) {
            #pragma unroll
            for (int c = 0; c <= NC; c++) red[c][tid] += red[c][tid + st];
        }
        __syncthreads();
    }
    if (tid == 0) {
        float lg[NC], m = -INFINITY, s = 0.f;
        #pragma unroll
        for (int c = 0; c < NC; c++) { lg[c] = red[c][0] + b[c]; m = fmaxf(m, lg[c]); }
        #pragma unroll
        for (int c = 0; c < NC; c++) { lg[c] = expf(lg[c] - m); s += lg[c]; }
        float inv = 1.f / s;
        #pragma unroll
        for (int c = 0; c < NC; c++) {
            float tv = 0.f;
            #pragma unroll
            for (int cc = 0; cc < NC; cc++) tv = fmaf(lg[cc] * inv, L[cc * NC + c], tv);
            t_out[row * NC + c] = tv;
        }
        xsn[row] = red[NC][0];
    }
}

// ---------------- fused softmax + (w @ atl) -> y [BATCH, NC] ----------------
__global__ void final_kernel(const float* __restrict__ logits, const float* __restrict__ atl,
                             float* __restrict__ y)
{
    constexpr int THREADS = 256;
    constexpr int PER = NS / THREADS;  // 32
    int row = blockIdx.x;
    int tid = threadIdx.x;
    const float* xr = logits + (size_t)row * NS;
    float r[PER];
    float mx = -INFINITY;
    #pragma unroll
    for (int i = 0; i < PER; i++) {
        r[i] = xr[tid + i * THREADS];
        mx = fmaxf(mx, r[i]);
    }
    __shared__ float sred[THREADS / 32];
    #pragma unroll
    for (int o = 16; o > 0; o >>= 1) mx = fmaxf(mx, __shfl_xor_sync(0xffffffffu, mx, o));
    if ((tid & 31) == 0) sred[tid >> 5] = mx;
    __syncthreads();
    {
        float m = sred[0];
        #pragma unroll
        for (int i = 1; i < THREADS / 32; i++) m = fmaxf(m, sred[i]);
        mx = m;
    }
    __syncthreads();

    float s = 0.f;
    float ya[NC];
    #pragma unroll
    for (int c = 0; c < NC; c++) ya[c] = 0.f;
    #pragma unroll
    for (int i = 0; i < PER; i++) {
        float e = expf(r[i] - mx);
        s += e;
        int j = tid + i * THREADS;
        const float* a = atl + (size_t)j * NC;
        #pragma unroll
        for (int c = 0; c < NC; c++) ya[c] = fmaf(e, __ldg(&a[c]), ya[c]);
    }
    __shared__ float red[NC + 1][THREADS];
    #pragma unroll
    for (int c = 0; c < NC; c++) red[c][tid] = ya[c];
    red[NC][tid] = s;
    __syncthreads();
    for (int st = THREADS / 2; st > 0; st >>= 1) {
        if (tid < st) {
            #pragma unroll
            for (int c = 0; c <= NC; c++) red[c][tid] += red[c][tid + st];
        }
        __syncthreads();
    }
    if (tid < NC) {
        y[row * NC + tid] = red[tid][0] / red[NC][0];
    }
}

// ---------------- launch ----------------
extern "C" void kernel_launch(void* const* d_in, const int* in_sizes, int n_in,
                              void* d_out, int out_size)
{
    const float* x   = (const float*)d_in[0];  // [B,32,32]
    const float* tf  = (const float*)d_in[1];  // [Nt,32,32]
    const float* asf = (const float*)d_in[2];  // [Nt,32,32]
    const float* sf  = (const float*)d_in[3];  // [Ns,32,32]
    const float* shl = (const float*)d_in[4];  // [Ns,C]
    const float* atl = (const float*)d_in[5];  // [Ns,C]
    const float* sld = (const float*)d_in[6];  // [C,C]
    const float* W   = (const float*)d_in[7];  // [D,C]
    const float* b   = (const float*)d_in[8];  // [C]
    float* y = (float*)d_out;                  // [B,C]

    float *logits, *xsrc, *tn, *sn, *xn, *xsn, *tbuf;
    cudaGetSymbolAddress((void**)&logits, g_logits);
    cudaGetSymbolAddress((void**)&xsrc,   g_xsrc);
    cudaGetSymbolAddress((void**)&tn,     g_tn);
    cudaGetSymbolAddress((void**)&sn,     g_sn);
    cudaGetSymbolAddress((void**)&xn,     g_xn);
    cudaGetSymbolAddress((void**)&xsn,    g_xsn);
    cudaGetSymbolAddress((void**)&tbuf,   g_t);

    // 1) row norms
    rownorm_kernel<<<NT, 256>>>(tf, tn, DIM);
    rownorm_kernel<<<NS, 256>>>(sf, sn, DIM);
    rownorm_kernel<<<BATCH, 256>>>(x, xn, DIM);

    // 2) feature-transport logits: -T * cdist(xf, tf)
    gemm_kernel<128, 128, 16, 8, 8, true, 1>
        <<<dim3(NT / 128, BATCH / 128), 256>>>(
            x, tf, logits, BATCH, NT, DIM, xn, tn, nullptr, nullptr);

    // 3) softmax over Nt
    softmax_rows_kernel<NT, 256><<<BATCH, 256>>>(logits);

    // 4) x_src = w_feat @ asf
    gemm_kernel<128, 64, 16, 8, 4, false, 0>
        <<<dim3(DIM / 64, BATCH / 128), 256>>>(
            logits, asf, xsrc, BATCH, DIM, NT, nullptr, nullptr, nullptr, nullptr);

    // 5) classifier head -> t = preds @ L, and ||x_src||^2
    preds_kernel<<<BATCH, 128>>>(xsrc, W, b, sld, tbuf, xsn);

    // 6) label-transport logits: -T * (cdist(x_src, sf) + t @ shl^T)
    gemm_kernel<128, 128, 16, 8, 8, true, 2>
        <<<dim3(NS / 128, BATCH / 128), 256>>>(
            xsrc, sf, logits, BATCH, NS, DIM, xsn, sn, tbuf, shl);

    // 7) softmax over Ns fused with y = w_lab @ atl
    final_kernel<<<BATCH, 256>>>(logits, atl, y);
}

// round 5
// speedup vs baseline: 1.0866x; 1.0866x over previous
#include <cuda_runtime.h>
#include <math.h>

// ---------------- problem constants ----------------
#define BATCH 1024
#define NT    8192
#define NS    8192
#define DIM   1024
#define NC    10
#define TEMP  100.0f

// ---------------- scratch (device globals; no allocation) ----------------
__device__ float g_logits[(size_t)BATCH * NT];   // 32 MB, reused for both softmax stages
__device__ float g_xsrc[BATCH * DIM];            // 4 MB
__device__ float g_tn[NT];
__device__ float g_sn[NS];
__device__ float g_xn[BATCH];
__device__ float g_xsn[BATCH];
__device__ float g_t[BATCH * NC];                // preds @ L

// ---------------- packed f32x2 helpers (sm_103a) ----------------
struct __align__(16) ULL2 { unsigned long long x, y; };

__device__ __forceinline__ unsigned long long dup_f32(float v) {
    unsigned long long r;
    asm("mov.b64 %0, {%1, %1};" : "=l"(r) : "r"(__float_as_uint(v)));
    return r;
}
__device__ __forceinline__ void ffma2(unsigned long long& c,
                                      unsigned long long a, unsigned long long b) {
    asm("fma.rn.f32x2 %0, %1, %2, %0;" : "+l"(c) : "l"(a), "l"(b));
}
__device__ __forceinline__ float2 unpack2(unsigned long long v) {
    float2 r;
    asm("mov.b64 {%0, %1}, %2;" : "=f"(r.x), "=f"(r.y) : "l"(v));
    return r;
}

// ---------------- row squared-norms ----------------
__global__ void rownorm_kernel(const float* __restrict__ X, float* __restrict__ out, int K) {
    int row = blockIdx.x;
    const float* xr = X + (size_t)row * K;
    float s = 0.f;
    for (int k = threadIdx.x * 4; k < K; k += blockDim.x * 4) {
        float4 v = *reinterpret_cast<const float4*>(xr + k);
        s += v.x * v.x + v.y * v.y + v.z * v.z + v.w * v.w;
    }
    #pragma unroll
    for (int o = 16; o > 0; o >>= 1) s += __shfl_xor_sync(0xffffffffu, s, o);
    __shared__ float ws[8];
    int wid = threadIdx.x >> 5, lid = threadIdx.x & 31;
    if (lid == 0) ws[wid] = s;
    __syncthreads();
    if (threadIdx.x == 0) {
        float t = 0.f;
        for (int i = 0; i < (int)(blockDim.x >> 5); i++) t += ws[i];
        out[row] = t;
    }
}

// ---------------- SGEMM (fp32, packed f32x2 inner loop), templated epilogue ----------------
// A: [M,K] row-major.  B: BT ? [N,K] : [K,N] row-major.
// MODE 0: C = A*B          (plain)
// MODE 1: C = -T*sqrt(max(rnA[m]+rnB[n]-2*acc, 1e-12))
// MODE 2: C = -T*(sqrt(...) + sum_c Tm[m,c]*SHL[n,c])
template<int BM, int BN, int BK, int TM, int TN, bool BT, int MODE>
__global__ void __launch_bounds__((BM / TM) * (BN / TN))
gemm_kernel(const float* __restrict__ A, const float* __restrict__ B,
            float* __restrict__ C, int M, int N, int K,
            const float* __restrict__ rnA, const float* __restrict__ rnB,
            const float* __restrict__ Tm, const float* __restrict__ SHL)
{
    constexpr int THREADS = (BM / TM) * (BN / TN);
    constexpr int PAD = 4;
    static_assert(TN % 4 == 0 || TN == 4, "TN pairs");
    __shared__ float As[BK][BM + PAD];
    __shared__ float Bs[BK][BN + PAD];

    const int tid = threadIdx.x;
    const int tx = tid % (BN / TN);
    const int ty = tid / (BN / TN);
    const int row0 = blockIdx.y * BM;
    const int col0 = blockIdx.x * BN;

    constexpr int TNP = TN / 2;
    unsigned long long acc[TM][TNP];
    #pragma unroll
    for (int i = 0; i < TM; i++)
        #pragma unroll
        for (int j = 0; j < TNP; j++) acc[i][j] = 0ull;

    // A tile load mapping: float4 along K
    constexpr int AK4 = BK / 4;
    const int a_r = tid / AK4;
    const int a_c = (tid % AK4) * 4;
    constexpr int A_IT = THREADS / AK4;

    // B tile load mappings
    constexpr int BK4 = BK / 4;       // for BT (B is [N,K])
    const int bt_r = tid / BK4;
    const int bt_c = (tid % BK4) * 4;
    constexpr int BT_IT = THREADS / BK4;

    constexpr int BN4 = BN / 4;       // for !BT (B is [K,N])
    const int bn_r = tid / BN4;
    const int bn_c = (tid % BN4) * 4;
    constexpr int BNR_IT = THREADS / BN4;

    for (int k0 = 0; k0 < K; k0 += BK) {
        // load A tile (transpose into As[k][m])
        #pragma unroll
        for (int it = 0; it < BM / A_IT; it++) {
            int r = a_r + it * A_IT;
            float4 v = *reinterpret_cast<const float4*>(A + (size_t)(row0 + r) * K + (k0 + a_c));
            As[a_c + 0][r] = v.x; As[a_c + 1][r] = v.y;
            As[a_c + 2][r] = v.z; As[a_c + 3][r] = v.w;
        }
        if (BT) {
            #pragma unroll
            for (int it = 0; it < BN / BT_IT; it++) {
                int r = bt_r + it * BT_IT;
                float4 v = *reinterpret_cast<const float4*>(B + (size_t)(col0 + r) * K + (k0 + bt_c));
                Bs[bt_c + 0][r] = v.x; Bs[bt_c + 1][r] = v.y;
                Bs[bt_c + 2][r] = v.z; Bs[bt_c + 3][r] = v.w;
            }
        } else {
            #pragma unroll
            for (int it = 0; it < BK / BNR_IT; it++) {
                int r = bn_r + it * BNR_IT;
                float4 v = *reinterpret_cast<const float4*>(B + (size_t)(k0 + r) * N + (col0 + bn_c));
                *reinterpret_cast<float4*>(&Bs[r][bn_c]) = v;
            }
        }
        __syncthreads();
        #pragma unroll
        for (int kk = 0; kk < BK; kk++) {
            float af[TM];
            #pragma unroll
            for (int i = 0; i < TM; i += 4)
                *reinterpret_cast<float4*>(&af[i]) =
                    *reinterpret_cast<const float4*>(&As[kk][ty * TM + i]);
            unsigned long long a2[TM];
            #pragma unroll
            for (int i = 0; i < TM; i++) a2[i] = dup_f32(af[i]);

            unsigned long long b2[TNP];
            #pragma unroll
            for (int j = 0; j < TNP; j += 2) {
                ULL2 t = *reinterpret_cast<const ULL2*>(&Bs[kk][tx * TN + 2 * j]);
                b2[j] = t.x; b2[j + 1] = t.y;
            }
            #pragma unroll
            for (int i = 0; i < TM; i++)
                #pragma unroll
                for (int j = 0; j < TNP; j++)
                    ffma2(acc[i][j], a2[i], b2[j]);
        }
        __syncthreads();
    }

    // unpack accumulators to scalars
    float accf[TM][TN];
    #pragma unroll
    for (int i = 0; i < TM; i++)
        #pragma unroll
        for (int j = 0; j < TNP; j++) {
            float2 p = unpack2(acc[i][j]);
            accf[i][2 * j] = p.x;
            accf[i][2 * j + 1] = p.y;
        }

    // ---------------- epilogue ----------------
    if (MODE == 0) {
        #pragma unroll
        for (int i = 0; i < TM; i++) {
            int gm = row0 + ty * TM + i;
            #pragma unroll
            for (int j = 0; j < TN; j += 4) {
                float4 v = make_float4(accf[i][j], accf[i][j + 1], accf[i][j + 2], accf[i][j + 3]);
                *reinterpret_cast<float4*>(&C[(size_t)gm * N + (col0 + tx * TN + j)]) = v;
            }
        }
    } else {
        float ra[TM];
        #pragma unroll
        for (int i = 0; i < TM; i++) ra[i] = __ldg(&rnA[row0 + ty * TM + i]);
        #pragma unroll
        for (int j = 0; j < TN; j++) {
            int gn = col0 + tx * TN + j;
            float rb = __ldg(&rnB[gn]);
            float sv[NC];
            if (MODE == 2) {
                #pragma unroll
                for (int c = 0; c < NC; c++) sv[c] = __ldg(&SHL[(size_t)gn * NC + c]);
            }
            #pragma unroll
            for (int i = 0; i < TM; i++) {
                int gm = row0 + ty * TM + i;
                float sq = ra[i] + rb - 2.f * accf[i][j];
                float d = sqrtf(fmaxf(sq, 1e-12f));
                if (MODE == 2) {
                    float lab = 0.f;
                    #pragma unroll
                    for (int c = 0; c < NC; c++)
                        lab = fmaf(__ldg(&Tm[gm * NC + c]), sv[c], lab);
                    d += lab;
                }
                C[(size_t)gm * N + gn] = -TEMP * d;
            }
        }
    }
}

// ---------------- in-place row softmax (rows of length NCOL) ----------------
template<int NCOL, int THREADS>
__global__ void softmax_rows_kernel(float* __restrict__ X) {
    constexpr int PER = NCOL / THREADS;
    int row = blockIdx.x;
    float* xr = X + (size_t)row * NCOL;
    int tid = threadIdx.x;
    float r[PER];
    float mx = -INFINITY;
    #pragma unroll
    for (int i = 0; i < PER; i++) {
        r[i] = xr[tid + i * THREADS];
        mx = fmaxf(mx, r[i]);
    }
    __shared__ float sred[THREADS / 32];
    #pragma unroll
    for (int o = 16; o > 0; o >>= 1) mx = fmaxf(mx, __shfl_xor_sync(0xffffffffu, mx, o));
    if ((tid & 31) == 0) sred[tid >> 5] = mx;
    __syncthreads();
    {
        float m = sred[0];
        #pragma unroll
        for (int i = 1; i < THREADS / 32; i++) m = fmaxf(m, sred[i]);
        mx = m;
    }
    __syncthreads();
    float s = 0.f;
    #pragma unroll
    for (int i = 0; i < PER; i++) {
        r[i] = expf(r[i] - mx);
        s += r[i];
    }
    #pragma unroll
    for (int o = 16; o > 0; o >>= 1) s += __shfl_xor_sync(0xffffffffu, s, o);
    if ((tid & 31) == 0) sred[tid >> 5] = s;
    __syncthreads();
    {
        float m = 0.f;
        #pragma unroll
        for (int i = 0; i < THREADS / 32; i++) m += sred[i];
        s = m;
    }
    float inv = 1.f / s;
    #pragma unroll
    for (int i = 0; i < PER; i++) xr[tid + i * THREADS] = r[i] * inv;
}

// ---------------- classifier head: preds = softmax(xsrc@W+b); t = preds@L; xsn ----------------
__global__ void preds_kernel(const float* __restrict__ xsrc, const float* __restrict__ W,
                             const float* __restrict__ b, const float* __restrict__ L,
                             float* __restrict__ t_out, float* __restrict__ xsn)
{
    int row = blockIdx.x;
    int tid = threadIdx.x;
    const float* xr = xsrc + (size_t)row * DIM;
    float acc[NC];
    #pragma unroll
    for (int c = 0; c < NC; c++) acc[c] = 0.f;
    float nrm = 0.f;
    for (int k = tid; k < DIM; k += blockDim.x) {
        float xv = xr[k];
        nrm = fmaf(xv, xv, nrm);
        #pragma unroll
        for (int c = 0; c < NC; c++) acc[c] = fmaf(xv, __ldg(&W[k * NC + c]), acc[c]);
    }
    __shared__ float red[NC + 1][128];
    #pragma unroll
    for (int c = 0; c < NC; c++) red[c][tid] = acc[c];
    red[NC][tid] = nrm;
    __syncthreads();
    for (int st = 64; st > 0; st >>= 1) {
        if (tid < st) {
            #pragma unroll
            for (int c = 0; c <= NC; c++) red[c][tid] += red[c][tid + st];
        }
        __syncthreads();
    }
    if (tid == 0) {
        float lg[NC], m = -INFINITY, s = 0.f;
        #pragma unroll
        for (int c = 0; c < NC; c++) { lg[c] = red[c][0] + b[c]; m = fmaxf(m, lg[c]); }
        #pragma unroll
        for (int c = 0; c < NC; c++) { lg[c] = expf(lg[c] - m); s += lg[c]; }
        float inv = 1.f / s;
        #pragma unroll
        for (int c = 0; c < NC; c++) {
            float tv = 0.f;
            #pragma unroll
            for (int cc = 0; cc < NC; cc++) tv = fmaf(lg[cc] * inv, L[cc * NC + c], tv);
            t_out[row * NC + c] = tv;
        }
        xsn[row] = red[NC][0];
    }
}

// ---------------- fused softmax + (w @ atl) -> y [BATCH, NC] ----------------
__global__ void final_kernel(const float* __restrict__ logits, const float* __restrict__ atl,
                             float* __restrict__ y)
{
    constexpr int THREADS = 256;
    constexpr int PER = NS / THREADS;  // 32
    int row = blockIdx.x;
    int tid = threadIdx.x;
    const float* xr = logits + (size_t)row * NS;
    float r[PER];
    float mx = -INFINITY;
    #pragma unroll
    for (int i = 0; i < PER; i++) {
        r[i] = xr[tid + i * THREADS];
        mx = fmaxf(mx, r[i]);
    }
    __shared__ float sred[THREADS / 32];
    #pragma unroll
    for (int o = 16; o > 0; o >>= 1) mx = fmaxf(mx, __shfl_xor_sync(0xffffffffu, mx, o));
    if ((tid & 31) == 0) sred[tid >> 5] = mx;
    __syncthreads();
    {
        float m = sred[0];
        #pragma unroll
        for (int i = 1; i < THREADS / 32; i++) m = fmaxf(m, sred[i]);
        mx = m;
    }
    __syncthreads();

    float s = 0.f;
    float ya[NC];
    #pragma unroll
    for (int c = 0; c < NC; c++) ya[c] = 0.f;
    #pragma unroll
    for (int i = 0; i < PER; i++) {
        float e = expf(r[i] - mx);
        s += e;
        int j = tid + i * THREADS;
        const float* a = atl + (size_t)j * NC;
        #pragma unroll
        for (int c = 0; c < NC; c++) ya[c] = fmaf(e, __ldg(&a[c]), ya[c]);
    }
    __shared__ float red[NC + 1][THREADS];
    #pragma unroll
    for (int c = 0; c < NC; c++) red[c][tid] = ya[c];
    red[NC][tid] = s;
    __syncthreads();
    for (int st = THREADS / 2; st > 0; st >>= 1) {
        if (tid < st) {
            #pragma unroll
            for (int c = 0; c <= NC; c++) red[c][tid] += red[c][tid + st];
        }
        __syncthreads();
    }
    if (tid < NC) {
        y[row * NC + tid] = red[tid][0] / red[NC][0];
    }
}

// ---------------- launch ----------------
extern "C" void kernel_launch(void* const* d_in, const int* in_sizes, int n_in,
                              void* d_out, int out_size)
{
    const float* x   = (const float*)d_in[0];  // [B,32,32]
    const float* tf  = (const float*)d_in[1];  // [Nt,32,32]
    const float* asf = (const float*)d_in[2];  // [Nt,32,32]
    const float* sf  = (const float*)d_in[3];  // [Ns,32,32]
    const float* shl = (const float*)d_in[4];  // [Ns,C]
    const float* atl = (const float*)d_in[5];  // [Ns,C]
    const float* sld = (const float*)d_in[6];  // [C,C]
    const float* W   = (const float*)d_in[7];  // [D,C]
    const float* b   = (const float*)d_in[8];  // [C]
    float* y = (float*)d_out;                  // [B,C]

    float *logits, *xsrc, *tn, *sn, *xn, *xsn, *tbuf;
    cudaGetSymbolAddress((void**)&logits, g_logits);
    cudaGetSymbolAddress((void**)&xsrc,   g_xsrc);
    cudaGetSymbolAddress((void**)&tn,     g_tn);
    cudaGetSymbolAddress((void**)&sn,     g_sn);
    cudaGetSymbolAddress((void**)&xn,     g_xn);
    cudaGetSymbolAddress((void**)&xsn,    g_xsn);
    cudaGetSymbolAddress((void**)&tbuf,   g_t);

    // 1) row norms
    rownorm_kernel<<<NT, 256>>>(tf, tn, DIM);
    rownorm_kernel<<<NS, 256>>>(sf, sn, DIM);
    rownorm_kernel<<<BATCH, 256>>>(x, xn, DIM);

    // 2) feature-transport logits: -T * cdist(xf, tf)
    gemm_kernel<128, 128, 16, 8, 8, true, 1>
        <<<dim3(NT / 128, BATCH / 128), 256>>>(
            x, tf, logits, BATCH, NT, DIM, xn, tn, nullptr, nullptr);

    // 3) softmax over Nt
    softmax_rows_kernel<NT, 256><<<BATCH, 256>>>(logits);

    // 4) x_src = w_feat @ asf  — retiled: 256 CTAs (was 128), BK=32
    gemm_kernel<64, 64, 32, 4, 4, false, 0>
        <<<dim3(DIM / 64, BATCH / 64), 256>>>(
            logits, asf, xsrc, BATCH, DIM, NT, nullptr, nullptr, nullptr, nullptr);

    // 5) classifier head -> t = preds @ L, and ||x_src||^2
    preds_kernel<<<BATCH, 128>>>(xsrc, W, b, sld, tbuf, xsn);

    // 6) label-transport logits: -T * (cdist(x_src, sf) + t @ shl^T)
    gemm_kernel<128, 128, 16, 8, 8, true, 2>
        <<<dim3(NS / 128, BATCH / 128), 256>>>(
            xsrc, sf, logits, BATCH, NS, DIM, xsn, sn, tbuf, shl);

    // 7) softmax over Ns fused with y = w_lab @ atl
    final_kernel<<<BATCH, 256>>>(logits, atl, y);
}

// round 7
// speedup vs baseline: 2.0108x; 1.8506x over previous
#include <cuda_runtime.h>
#include <cuda_bf16.h>
#include <math.h>
#include <stdint.h>

// ---------------- problem constants ----------------
#define BATCH 1024
#define NT    8192
#define NS    8192
#define DIM   1024
#define NC    10
#define TEMP  100.0f

// ---------------- scratch (device globals; no allocation) ----------------
__device__ float g_logits[(size_t)BATCH * NT];   // 32 MB
__device__ float g_xsrc[BATCH * DIM];
__device__ float g_tn[NT];
__device__ float g_sn[NS];
__device__ float g_xn[BATCH];
__device__ float g_xsn[BATCH];
__device__ float g_t[BATCH * NC];
// bf16 split-2 operand buffers (hi at offset 0, lo at offset SZ)
__device__ __nv_bfloat16 g_x2  [(size_t)2 * BATCH * DIM];
__device__ __nv_bfloat16 g_tf2 [(size_t)2 * NT * DIM];
__device__ __nv_bfloat16 g_sf2 [(size_t)2 * NS * DIM];
__device__ __nv_bfloat16 g_asfT2[(size_t)2 * DIM * NT];   // asf transposed: [DIM, NT]
__device__ __nv_bfloat16 g_w2  [(size_t)2 * BATCH * NT];
__device__ __nv_bfloat16 g_xs2 [(size_t)2 * BATCH * DIM];

// ===================== asm helpers (all sm_80-era PTX; compiles for compute_103) =====================
__device__ __forceinline__ uint32_t smem_to_u32(const void* smem_ptr) {
    uint32_t addr;
    asm("{ .reg .u64 tmp; cvta.to.shared.u64 tmp, %1; cvt.u32.u64 %0, tmp; }"
        : "=r"(addr) : "l"(smem_ptr));
    return addr;
}
#define CP_ASYNC_CG16(dst, src) \
    asm volatile("cp.async.cg.shared.global [%0], [%1], 16;" :: "r"(dst), "l"(src))
#define CP_COMMIT() asm volatile("cp.async.commit_group;" ::: "memory")
#define CP_WAIT(n)  asm volatile("cp.async.wait_group %0;" :: "n"(n) : "memory")
#define LDSM_X4(r0, r1, r2, r3, addr) \
    asm volatile("ldmatrix.sync.aligned.m8n8.x4.shared.b16 {%0,%1,%2,%3}, [%4];" \
        : "=r"(r0), "=r"(r1), "=r"(r2), "=r"(r3) : "r"(addr))
#define MMA_16816(d, a, b) \
    asm volatile("mma.sync.aligned.m16n8k16.row.col.f32.bf16.bf16.f32 " \
        "{%0,%1,%2,%3}, {%4,%5,%6,%7}, {%8,%9}, {%0,%1,%2,%3};" \
        : "+f"((d)[0]), "+f"((d)[1]), "+f"((d)[2]), "+f"((d)[3]) \
        : "r"((a)[0]), "r"((a)[1]), "r"((a)[2]), "r"((a)[3]), \
          "r"((b)[0]), "r"((b)[1]))

// ===================== bf16 split-2 conversion =====================
__device__ __forceinline__ void split2_one(float x, __nv_bfloat16& b0, __nv_bfloat16& b1) {
    b0 = __float2bfloat16(x);
    b1 = __float2bfloat16(x - __bfloat162float(b0));
}

__global__ void split2_kernel(const float4* __restrict__ X,
                              __nv_bfloat162* __restrict__ O0,
                              __nv_bfloat162* __restrict__ O1, int n4) {
    int i = blockIdx.x * blockDim.x + threadIdx.x;
    if (i >= n4) return;
    float4 v = X[i];
    __nv_bfloat16 a0, a1, b0, b1, c0, c1, d0, d1;
    split2_one(v.x, a0, a1);
    split2_one(v.y, b0, b1);
    split2_one(v.z, c0, c1);
    split2_one(v.w, d0, d1);
    O0[2 * i] = __halves2bfloat162(a0, b0); O0[2 * i + 1] = __halves2bfloat162(c0, d0);
    O1[2 * i] = __halves2bfloat162(a1, b1); O1[2 * i + 1] = __halves2bfloat162(c1, d1);
}

// transpose + split2: X [R, Cc] fp32 -> O* [Cc, R] bf16
__global__ void split2T_kernel(const float* __restrict__ X,
                               __nv_bfloat16* __restrict__ O0,
                               __nv_bfloat16* __restrict__ O1, int R, int Cc) {
    __shared__ float t[32][33];
    int tx = threadIdx.x, ty = threadIdx.y;
    int r = blockIdx.y * 32 + ty;
    int c = blockIdx.x * 32 + tx;
    t[ty][tx] = X[(size_t)r * Cc + c];
    __syncthreads();
    int orow = blockIdx.x * 32 + ty;
    int ocol = blockIdx.y * 32 + tx;
    float x = t[tx][ty];
    __nv_bfloat16 b0, b1;
    split2_one(x, b0, b1);
    size_t o = (size_t)orow * R + ocol;
    O0[o] = b0; O1[o] = b1;
}

// ===================== row squared-norms =====================
__global__ void rownorm_kernel(const float* __restrict__ X, float* __restrict__ out, int K) {
    int row = blockIdx.x;
    const float* xr = X + (size_t)row * K;
    float s = 0.f;
    for (int k = threadIdx.x * 4; k < K; k += blockDim.x * 4) {
        float4 v = *reinterpret_cast<const float4*>(xr + k);
        s += v.x * v.x + v.y * v.y + v.z * v.z + v.w * v.w;
    }
    #pragma unroll
    for (int o = 16; o > 0; o >>= 1) s += __shfl_xor_sync(0xffffffffu, s, o);
    __shared__ float ws[8];
    int wid = threadIdx.x >> 5, lid = threadIdx.x & 31;
    if (lid == 0) ws[wid] = s;
    __syncthreads();
    if (threadIdx.x == 0) {
        float t = 0.f;
        for (int i = 0; i < (int)(blockDim.x >> 5); i++) t += ws[i];
        out[row] = t;
    }
}

// ===================== mma.sync bf16 split-2 GEMM =====================
// Logical GEMM: C[M,N] = Afp32[M,K] @ Bfp32[N,K]^T via 3 bf16 products
//   acc = A0*B0 + A0*B1 + A1*B0   (A = A0 + A1, B = B0 + B1; drop A1*B1)
// MODE 0: C = acc
// MODE 1: C = -T*sqrt(max(rnA+rnB-2acc, 1e-12))
// MODE 2: MODE1 + label cost  -T*(d + sum_c Tm[m,c]*SHL[n,c])
#define KSTRIDE 40   // 32 used + 8 pad (bf16 elems) -> conflict-free ldmatrix

template<int BM, int BN, int THREADS>
__device__ __forceinline__ void load_stage_fn(
    const __nv_bfloat16* __restrict__ A0g, const __nv_bfloat16* __restrict__ A1g,
    const __nv_bfloat16* __restrict__ B0g, const __nv_bfloat16* __restrict__ B1g,
    uint32_t smem_u32, int st, int k0, int row0, int col0, int K, int tid)
{
    constexpr int TOT_A = BM * 8;           // 2 splits * BM rows * 4 chunks
    constexpr int CPT = (BM + BN) * 8 / THREADS;
    #pragma unroll
    for (int t = 0; t < CPT; t++) {
        int i = tid + t * THREADS;
        if (i < TOT_A) {
            int sp = i / (BM * 4);
            int rr = (i >> 2) % BM;
            int kc = i & 3;
            const __nv_bfloat16* g = sp ? A1g : A0g;
            const __nv_bfloat16* src = g + (size_t)(row0 + rr) * K + k0 + kc * 8;
            uint32_t dst = smem_u32 + 2u * (uint32_t)(((st * 2 + sp) * BM + rr) * KSTRIDE + kc * 8);
            CP_ASYNC_CG16(dst, src);
        } else {
            int j = i - TOT_A;
            int sp = j / (BN * 4);
            int rr = (j >> 2) % BN;
            int kc = j & 3;
            const __nv_bfloat16* g = sp ? B1g : B0g;
            const __nv_bfloat16* src = g + (size_t)(col0 + rr) * K + k0 + kc * 8;
            uint32_t dst = smem_u32 +
                2u * (uint32_t)(4 * BM * KSTRIDE + ((st * 2 + sp) * BN + rr) * KSTRIDE + kc * 8);
            CP_ASYNC_CG16(dst, src);
        }
    }
}

template<int BM, int BN, int WM, int WN, int MODE>
__global__ void __launch_bounds__((BM / WM) * (BN / WN) * 32, 1)
mma_gemm_kernel(const __nv_bfloat16* __restrict__ A0g, const __nv_bfloat16* __restrict__ A1g,
                const __nv_bfloat16* __restrict__ B0g, const __nv_bfloat16* __restrict__ B1g,
                float* __restrict__ C, int N, int K,
                const float* __restrict__ rnA, const float* __restrict__ rnB,
                const float* __restrict__ Tm, const float* __restrict__ SHL)
{
    constexpr int THREADS = (BM / WM) * (BN / WN) * 32;
    constexpr int MB = WM / 16;
    constexpr int NB = WN / 8;
    constexpr int NB2 = WN / 16;
    constexpr int A_ELEMS = 4 * BM * KSTRIDE;   // 2 stages * 2 splits
    constexpr int B_ELEMS = 4 * BN * KSTRIDE;

    extern __shared__ char smem[];
    const uint32_t smem_u32 = smem_to_u32(smem);
    const int tid = threadIdx.x;
    const int wid = tid >> 5;
    const int lane = tid & 31;
    const int warps_n = BN / WN;
    const int wm0 = (wid / warps_n) * WM;
    const int wn0 = (wid % warps_n) * WN;
    const int row0 = blockIdx.y * BM;
    const int col0 = blockIdx.x * BN;

    float* sTm  = reinterpret_cast<float*>(smem + 2 * (A_ELEMS + B_ELEMS));
    float* sShl = sTm + BM * NC;
    if (MODE == 2) {
        for (int i = tid; i < BM * NC; i += THREADS)
            sTm[i] = __ldg(&Tm[(size_t)(row0 + i / NC) * NC + (i % NC)]);
        for (int i = tid; i < BN * NC; i += THREADS)
            sShl[i] = __ldg(&SHL[(size_t)(col0 + i / NC) * NC + (i % NC)]);
    }

    float acc[MB][NB][4];
    #pragma unroll
    for (int i = 0; i < MB; i++)
        #pragma unroll
        for (int j = 0; j < NB; j++)
            #pragma unroll
            for (int q = 0; q < 4; q++) acc[i][j][q] = 0.f;

    const int nch = K >> 5;   // BK = 32
    load_stage_fn<BM, BN, THREADS>(A0g, A1g, B0g, B1g, smem_u32, 0, 0, row0, col0, K, tid);
    CP_COMMIT();

    // per-thread ldmatrix address components
    const int lrow = lane & 15;
    const int lcol = (lane >> 4) << 3;

    for (int c = 0; c < nch; c++) {
        if (c + 1 < nch) {
            load_stage_fn<BM, BN, THREADS>(A0g, A1g, B0g, B1g, smem_u32,
                                           (c + 1) & 1, (c + 1) << 5, row0, col0, K, tid);
            CP_COMMIT();
            CP_WAIT(1);
        } else {
            CP_WAIT(0);
        }
        __syncthreads();
        const int st = c & 1;

        #pragma unroll
        for (int s16 = 0; s16 < 32; s16 += 16) {
            uint32_t Af[2][MB][4];
            uint32_t Bf[2][NB][2];
            #pragma unroll
            for (int sp = 0; sp < 2; sp++) {
                #pragma unroll
                for (int mb = 0; mb < MB; mb++) {
                    uint32_t addr = smem_u32 + 2u * (uint32_t)(
                        ((st * 2 + sp) * BM + wm0 + mb * 16 + lrow) * KSTRIDE + s16 + lcol);
                    LDSM_X4(Af[sp][mb][0], Af[sp][mb][1], Af[sp][mb][2], Af[sp][mb][3], addr);
                }
                #pragma unroll
                for (int nb2 = 0; nb2 < NB2; nb2++) {
                    uint32_t r0, r1, r2, r3;
                    uint32_t addr = smem_u32 + 2u * (uint32_t)(
                        4 * BM * KSTRIDE +
                        ((st * 2 + sp) * BN + wn0 + nb2 * 16 + lrow) * KSTRIDE + s16 + lcol);
                    LDSM_X4(r0, r1, r2, r3, addr);
                    Bf[sp][2 * nb2][0] = r0;     Bf[sp][2 * nb2][1] = r2;
                    Bf[sp][2 * nb2 + 1][0] = r1; Bf[sp][2 * nb2 + 1][1] = r3;
                }
            }
            #pragma unroll
            for (int mb = 0; mb < MB; mb++)
                #pragma unroll
                for (int nb = 0; nb < NB; nb++) {
                    MMA_16816(acc[mb][nb], Af[0][mb], Bf[0][nb]);
                    MMA_16816(acc[mb][nb], Af[0][mb], Bf[1][nb]);
                    MMA_16816(acc[mb][nb], Af[1][mb], Bf[0][nb]);
                }
        }
        __syncthreads();
    }

    // ---------------- epilogue (direct from accumulator frags) ----------------
    const int lr = lane >> 2;
    const int lc = (lane & 3) * 2;
    #pragma unroll
    for (int mb = 0; mb < MB; mb++) {
        #pragma unroll
        for (int rr2 = 0; rr2 < 2; rr2++) {
            const int rg = row0 + wm0 + mb * 16 + lr + rr2 * 8;
            float ra = 0.f, tm[NC];
            if (MODE != 0) ra = __ldg(&rnA[rg]);
            if (MODE == 2) {
                #pragma unroll
                for (int cc = 0; cc < NC; cc++) tm[cc] = sTm[(rg - row0) * NC + cc];
            }
            #pragma unroll
            for (int nb = 0; nb < NB; nb++) {
                const int cg = col0 + wn0 + nb * 8 + lc;
                float v0 = acc[mb][nb][rr2 * 2];
                float v1 = acc[mb][nb][rr2 * 2 + 1];
                if (MODE != 0) {
                    float rb0 = __ldg(&rnB[cg]);
                    float rb1 = __ldg(&rnB[cg + 1]);
                    float d0 = sqrtf(fmaxf(ra + rb0 - 2.f * v0, 1e-12f));
                    float d1 = sqrtf(fmaxf(ra + rb1 - 2.f * v1, 1e-12f));
                    if (MODE == 2) {
                        float l0 = 0.f, l1 = 0.f;
                        #pragma unroll
                        for (int cc = 0; cc < NC; cc++) {
                            l0 = fmaf(tm[cc], sShl[(cg - col0) * NC + cc], l0);
                            l1 = fmaf(tm[cc], sShl[(cg + 1 - col0) * NC + cc], l1);
                        }
                        d0 += l0; d1 += l1;
                    }
                    v0 = -TEMP * d0; v1 = -TEMP * d1;
                }
                *reinterpret_cast<float2*>(&C[(size_t)rg * N + cg]) = make_float2(v0, v1);
            }
        }
    }
}

// ===================== row softmax =====================
template<int NCOL, int THREADS>
__global__ void softmax_rows_kernel(float* __restrict__ X) {
    constexpr int PER = NCOL / THREADS;
    int row = blockIdx.x;
    float* xr = X + (size_t)row * NCOL;
    int tid = threadIdx.x;
    float r[PER];
    float mx = -INFINITY;
    #pragma unroll
    for (int i = 0; i < PER; i++) {
        r[i] = xr[tid + i * THREADS];
        mx = fmaxf(mx, r[i]);
    }
    __shared__ float sred[THREADS / 32];
    #pragma unroll
    for (int o = 16; o > 0; o >>= 1) mx = fmaxf(mx, __shfl_xor_sync(0xffffffffu, mx, o));
    if ((tid & 31) == 0) sred[tid >> 5] = mx;
    __syncthreads();
    {
        float m = sred[0];
        #pragma unroll
        for (int i = 1; i < THREADS / 32; i++) m = fmaxf(m, sred[i]);
        mx = m;
    }
    __syncthreads();
    float s = 0.f;
    #pragma unroll
    for (int i = 0; i < PER; i++) {
        r[i] = expf(r[i] - mx);
        s += r[i];
    }
    #pragma unroll
    for (int o = 16; o > 0; o >>= 1) s += __shfl_xor_sync(0xffffffffu, s, o);
    if ((tid & 31) == 0) sred[tid >> 5] = s;
    __syncthreads();
    {
        float m = 0.f;
        #pragma unroll
        for (int i = 0; i < THREADS / 32; i++) m += sred[i];
        s = m;
    }
    float inv = 1.f / s;
    #pragma unroll
    for (int i = 0; i < PER; i++) xr[tid + i * THREADS] = r[i] * inv;
}

// ===================== classifier head =====================
__global__ void preds_kernel(const float* __restrict__ xsrc, const float* __restrict__ W,
                             const float* __restrict__ b, const float* __restrict__ L,
                             float* __restrict__ t_out, float* __restrict__ xsn)
{
    int row = blockIdx.x;
    int tid = threadIdx.x;
    const float* xr = xsrc + (size_t)row * DIM;
    float acc[NC];
    #pragma unroll
    for (int c = 0; c < NC; c++) acc[c] = 0.f;
    float nrm = 0.f;
    for (int k = tid; k < DIM; k += blockDim.x) {
        float xv = xr[k];
        nrm = fmaf(xv, xv, nrm);
        #pragma unroll
        for (int c = 0; c < NC; c++) acc[c] = fmaf(xv, __ldg(&W[k * NC + c]), acc[c]);
    }
    __shared__ float red[NC + 1][128];
    #pragma unroll
    for (int c = 0; c < NC; c++) red[c][tid] = acc[c];
    red[NC][tid] = nrm;
    __syncthreads();
    for (int st = 64; st > 0; st >>= 1) {
        if (tid < st) {
            #pragma unroll
            for (int c = 0; c <= NC; c++) red[c][tid] += red[c][tid + st];
        }
        __syncthreads();
    }
    if (tid == 0) {
        float lg[NC], m = -INFINITY, s = 0.f;
        #pragma unroll
        for (int c = 0; c < NC; c++) { lg[c] = red[c][0] + b[c]; m = fmaxf(m, lg[c]); }
        #pragma unroll
        for (int c = 0; c < NC; c++) { lg[c] = expf(lg[c] - m); s += lg[c]; }
        float inv = 1.f / s;
        #pragma unroll
        for (int c = 0; c < NC; c++) {
            float tv = 0.f;
            #pragma unroll
            for (int cc = 0; cc < NC; cc++) tv = fmaf(lg[cc] * inv, L[cc * NC + c], tv);
            t_out[row * NC + c] = tv;
        }
        xsn[row] = red[NC][0];
    }
}

// ===================== fused softmax + (w @ atl) =====================
__global__ void final_kernel(const float* __restrict__ logits, const float* __restrict__ atl,
                             float* __restrict__ y)
{
    constexpr int THREADS = 256;
    constexpr int PER = NS / THREADS;
    int row = blockIdx.x;
    int tid = threadIdx.x;
    const float* xr = logits + (size_t)row * NS;
    float r[PER];
    float mx = -INFINITY;
    #pragma unroll
    for (int i = 0; i < PER; i++) {
        r[i] = xr[tid + i * THREADS];
        mx = fmaxf(mx, r[i]);
    }
    __shared__ float sred[THREADS / 32];
    #pragma unroll
    for (int o = 16; o > 0; o >>= 1) mx = fmaxf(mx, __shfl_xor_sync(0xffffffffu, mx, o));
    if ((tid & 31) == 0) sred[tid >> 5] = mx;
    __syncthreads();
    {
        float m = sred[0];
        #pragma unroll
        for (int i = 1; i < THREADS / 32; i++) m = fmaxf(m, sred[i]);
        mx = m;
    }
    __syncthreads();

    float s = 0.f;
    float ya[NC];
    #pragma unroll
    for (int c = 0; c < NC; c++) ya[c] = 0.f;
    #pragma unroll
    for (int i = 0; i < PER; i++) {
        float e = expf(r[i] - mx);
        s += e;
        int j = tid + i * THREADS;
        const float* a = atl + (size_t)j * NC;
        #pragma unroll
        for (int c = 0; c < NC; c++) ya[c] = fmaf(e, __ldg(&a[c]), ya[c]);
    }
    __shared__ float red[NC + 1][THREADS];
    #pragma unroll
    for (int c = 0; c < NC; c++) red[c][tid] = ya[c];
    red[NC][tid] = s;
    __syncthreads();
    for (int st = THREADS / 2; st > 0; st >>= 1) {
        if (tid < st) {
            #pragma unroll
            for (int c = 0; c <= NC; c++) red[c][tid] += red[c][tid + st];
        }
        __syncthreads();
    }
    if (tid < NC) {
        y[row * NC + tid] = red[tid][0] / red[NC][0];
    }
}

// ===================== launch =====================
extern "C" void kernel_launch(void* const* d_in, const int* in_sizes, int n_in,
                              void* d_out, int out_size)
{
    const float* x   = (const float*)d_in[0];
    const float* tf  = (const float*)d_in[1];
    const float* asf = (const float*)d_in[2];
    const float* sf  = (const float*)d_in[3];
    const float* shl = (const float*)d_in[4];
    const float* atl = (const float*)d_in[5];
    const float* sld = (const float*)d_in[6];
    const float* W   = (const float*)d_in[7];
    const float* b   = (const float*)d_in[8];
    float* y = (float*)d_out;

    float *logits, *xsrc, *tn, *sn, *xn, *xsn, *tbuf;
    __nv_bfloat16 *x2, *tf2, *sf2, *asfT2, *w2, *xs2;
    cudaGetSymbolAddress((void**)&logits, g_logits);
    cudaGetSymbolAddress((void**)&xsrc,   g_xsrc);
    cudaGetSymbolAddress((void**)&tn,     g_tn);
    cudaGetSymbolAddress((void**)&sn,     g_sn);
    cudaGetSymbolAddress((void**)&xn,     g_xn);
    cudaGetSymbolAddress((void**)&xsn,    g_xsn);
    cudaGetSymbolAddress((void**)&tbuf,   g_t);
    cudaGetSymbolAddress((void**)&x2,     g_x2);
    cudaGetSymbolAddress((void**)&tf2,    g_tf2);
    cudaGetSymbolAddress((void**)&sf2,    g_sf2);
    cudaGetSymbolAddress((void**)&asfT2,  g_asfT2);
    cudaGetSymbolAddress((void**)&w2,     g_w2);
    cudaGetSymbolAddress((void**)&xs2,    g_xs2);

    // smem sizes: tiles = 2B * 4*(BM+BN)*KSTRIDE; + label region for MODE2
    const int smem_big   = 2 * 4 * (128 + 128) * KSTRIDE + 2 * 128 * NC * 4;  // 92160
    const int smem_small = 2 * 4 * (64 + 64) * KSTRIDE;                        // 40960
    cudaFuncSetAttribute(mma_gemm_kernel<128, 128, 64, 32, 1>,
                         cudaFuncAttributeMaxDynamicSharedMemorySize, smem_big);
    cudaFuncSetAttribute(mma_gemm_kernel<128, 128, 64, 32, 2>,
                         cudaFuncAttributeMaxDynamicSharedMemorySize, smem_big);
    cudaFuncSetAttribute(mma_gemm_kernel<64, 64, 32, 32, 0>,
                         cudaFuncAttributeMaxDynamicSharedMemorySize, smem_small);

    const size_t SZ_XD = (size_t)BATCH * DIM;
    const size_t SZ_TD = (size_t)NT * DIM;
    const size_t SZ_SD = (size_t)NS * DIM;
    const size_t SZ_DT = (size_t)DIM * NT;
    const size_t SZ_BN = (size_t)BATCH * NT;

    // 1) row norms (exact fp32)
    rownorm_kernel<<<NT, 256>>>(tf, tn, DIM);
    rownorm_kernel<<<NS, 256>>>(sf, sn, DIM);
    rownorm_kernel<<<BATCH, 256>>>(x, xn, DIM);

    // 2) split-2 conversions
    split2_kernel<<<(int)(SZ_XD / 4 + 255) / 256, 256>>>(
        (const float4*)x, (__nv_bfloat162*)x2, (__nv_bfloat162*)(x2 + SZ_XD), (int)(SZ_XD / 4));
    split2_kernel<<<(int)(SZ_TD / 4 + 255) / 256, 256>>>(
        (const float4*)tf, (__nv_bfloat162*)tf2, (__nv_bfloat162*)(tf2 + SZ_TD), (int)(SZ_TD / 4));
    split2_kernel<<<(int)(SZ_SD / 4 + 255) / 256, 256>>>(
        (const float4*)sf, (__nv_bfloat162*)sf2, (__nv_bfloat162*)(sf2 + SZ_SD), (int)(SZ_SD / 4));
    split2T_kernel<<<dim3(DIM / 32, NT / 32), dim3(32, 32)>>>(
        asf, asfT2, asfT2 + SZ_DT, NT, DIM);

    // 3) feature-transport logits: -T * cdist(xf, tf)   [1024 x 8192]
    mma_gemm_kernel<128, 128, 64, 32, 1><<<dim3(NT / 128, BATCH / 128), 256, smem_big>>>(
        x2, x2 + SZ_XD, tf2, tf2 + SZ_TD, logits, NT, DIM, xn, tn, nullptr, nullptr);

    // 4) softmax over Nt
    softmax_rows_kernel<NT, 256><<<BATCH, 256>>>(logits);

    // 5) split weights, then x_src = w_feat @ asf   [1024 x 1024], K = 8192
    split2_kernel<<<(int)(SZ_BN / 4 + 255) / 256, 256>>>(
        (const float4*)logits, (__nv_bfloat162*)w2, (__nv_bfloat162*)(w2 + SZ_BN), (int)(SZ_BN / 4));
    mma_gemm_kernel<64, 64, 32, 32, 0><<<dim3(DIM / 64, BATCH / 64), 128, smem_small>>>(
        w2, w2 + SZ_BN, asfT2, asfT2 + SZ_DT, xsrc, DIM, NT,
        nullptr, nullptr, nullptr, nullptr);

    // 6) classifier head -> tbuf = preds @ L, and ||x_src||^2
    preds_kernel<<<BATCH, 128>>>(xsrc, W, b, sld, tbuf, xsn);

    // 7) split x_src, then label-transport logits  [1024 x 8192]
    split2_kernel<<<(int)(SZ_XD / 4 + 255) / 256, 256>>>(
        (const float4*)xsrc, (__nv_bfloat162*)xs2, (__nv_bfloat162*)(xs2 + SZ_XD), (int)(SZ_XD / 4));
    mma_gemm_kernel<128, 128, 64, 32, 2><<<dim3(NS / 128, BATCH / 128), 256, smem_big>>>(
        xs2, xs2 + SZ_XD, sf2, sf2 + SZ_SD, logits, NS, DIM, xsn, sn, tbuf, shl);

    // 8) softmax over Ns fused with y = w_lab @ atl
    final_kernel<<<BATCH, 256>>>(logits, atl, y);
}

// round 8
// speedup vs baseline: 2.1278x; 1.0582x over previous
#include <cuda_runtime.h>
#include <cuda_bf16.h>
#include <math.h>
#include <stdint.h>

// ---------------- problem constants ----------------
#define BATCH 1024
#define NT    8192
#define NS    8192
#define DIM   1024
#define NC    10
#define TEMP  100.0f

// ---------------- scratch (device globals; no allocation) ----------------
__device__ float g_logits[(size_t)BATCH * NT];   // 32 MB
__device__ float g_xsrc[BATCH * DIM];
__device__ float g_tn[NT];
__device__ float g_sn[NS];
__device__ float g_xn[BATCH];
__device__ float g_xsn[BATCH];
__device__ float g_t[BATCH * NC];
// bf16 split-2 operand buffers (hi at offset 0, lo at offset SZ)
__device__ __nv_bfloat16 g_x2  [(size_t)2 * BATCH * DIM];
__device__ __nv_bfloat16 g_tf2 [(size_t)2 * NT * DIM];
__device__ __nv_bfloat16 g_sf2 [(size_t)2 * NS * DIM];
__device__ __nv_bfloat16 g_asfT2[(size_t)2 * DIM * NT];   // asf transposed: [DIM, NT]
__device__ __nv_bfloat16 g_w2  [(size_t)2 * BATCH * NT];
__device__ __nv_bfloat16 g_xs2 [(size_t)2 * BATCH * DIM];

// ===================== asm helpers (sm_80-era PTX; compiles for compute_103) =====================
__device__ __forceinline__ uint32_t smem_to_u32(const void* smem_ptr) {
    uint32_t addr;
    asm("{ .reg .u64 tmp; cvta.to.shared.u64 tmp, %1; cvt.u32.u64 %0, tmp; }"
        : "=r"(addr) : "l"(smem_ptr));
    return addr;
}
#define CP_ASYNC_CG16(dst, src) \
    asm volatile("cp.async.cg.shared.global [%0], [%1], 16;" :: "r"(dst), "l"(src))
#define CP_COMMIT() asm volatile("cp.async.commit_group;" ::: "memory")
#define CP_WAIT(n)  asm volatile("cp.async.wait_group %0;" :: "n"(n) : "memory")
#define LDSM_X4(r0, r1, r2, r3, addr) \
    asm volatile("ldmatrix.sync.aligned.m8n8.x4.shared.b16 {%0,%1,%2,%3}, [%4];" \
        : "=r"(r0), "=r"(r1), "=r"(r2), "=r"(r3) : "r"(addr))
#define MMA_16816(d, a, b) \
    asm volatile("mma.sync.aligned.m16n8k16.row.col.f32.bf16.bf16.f32 " \
        "{%0,%1,%2,%3}, {%4,%5,%6,%7}, {%8,%9}, {%0,%1,%2,%3};" \
        : "+f"((d)[0]), "+f"((d)[1]), "+f"((d)[2]), "+f"((d)[3]) \
        : "r"((a)[0]), "r"((a)[1]), "r"((a)[2]), "r"((a)[3]), \
          "r"((b)[0]), "r"((b)[1]))

// ===================== bf16 split-2 =====================
__device__ __forceinline__ void split2_one(float x, __nv_bfloat16& b0, __nv_bfloat16& b1) {
    b0 = __float2bfloat16(x);
    b1 = __float2bfloat16(x - __bfloat162float(b0));
}

// fused: row squared-norm + split-2 (one pass over X)
// X: [R, 1024] fp32. One block (256 thr) per row, 4 elems/thread.
__global__ void norm_split2_kernel(const float* __restrict__ X,
                                   __nv_bfloat16* __restrict__ O0,
                                   __nv_bfloat16* __restrict__ O1,
                                   float* __restrict__ norms) {
    int row = blockIdx.x;
    int tid = threadIdx.x;
    const float* xr = X + (size_t)row * DIM;
    float4 v = *reinterpret_cast<const float4*>(xr + tid * 4);
    float s = v.x * v.x + v.y * v.y + v.z * v.z + v.w * v.w;
    __nv_bfloat16 a0, a1, b0, b1, c0, c1, d0, d1;
    split2_one(v.x, a0, a1);
    split2_one(v.y, b0, b1);
    split2_one(v.z, c0, c1);
    split2_one(v.w, d0, d1);
    size_t o = (size_t)row * DIM + tid * 4;
    *reinterpret_cast<__nv_bfloat162*>(O0 + o)     = __halves2bfloat162(a0, b0);
    *reinterpret_cast<__nv_bfloat162*>(O0 + o + 2) = __halves2bfloat162(c0, d0);
    *reinterpret_cast<__nv_bfloat162*>(O1 + o)     = __halves2bfloat162(a1, b1);
    *reinterpret_cast<__nv_bfloat162*>(O1 + o + 2) = __halves2bfloat162(c1, d1);
    #pragma unroll
    for (int off = 16; off > 0; off >>= 1) s += __shfl_xor_sync(0xffffffffu, s, off);
    __shared__ float ws[8];
    if ((tid & 31) == 0) ws[tid >> 5] = s;
    __syncthreads();
    if (tid == 0) {
        float t = 0.f;
        #pragma unroll
        for (int i = 0; i < 8; i++) t += ws[i];
        norms[row] = t;
    }
}

// transpose + split2: X [R, Cc] fp32 -> O* [Cc, R] bf16
__global__ void split2T_kernel(const float* __restrict__ X,
                               __nv_bfloat16* __restrict__ O0,
                               __nv_bfloat16* __restrict__ O1, int R, int Cc) {
    __shared__ float t[32][33];
    int tx = threadIdx.x, ty = threadIdx.y;
    int r = blockIdx.y * 32 + ty;
    int c = blockIdx.x * 32 + tx;
    t[ty][tx] = X[(size_t)r * Cc + c];
    __syncthreads();
    int orow = blockIdx.x * 32 + ty;
    int ocol = blockIdx.y * 32 + tx;
    float x = t[tx][ty];
    __nv_bfloat16 b0, b1;
    split2_one(x, b0, b1);
    size_t o = (size_t)orow * R + ocol;
    O0[o] = b0; O1[o] = b1;
}

// ===================== mma.sync bf16 split-2 GEMM =====================
// acc = A0*B0 + A0*B1 + A1*B0   (A = A0 + A1, B = B0 + B1; drop A1*B1)
// MODE 0: C = acc
// MODE 1: C = -T*sqrt(max(rnA+rnB-2acc, 1e-12))
// MODE 2: MODE1 + label cost
#define KSTRIDE 40   // 32 used + 8 pad (bf16 elems) -> conflict-free ldmatrix

template<int BM, int BN, int THREADS, int STAGES>
__device__ __forceinline__ void load_stage_fn(
    const __nv_bfloat16* __restrict__ A0g, const __nv_bfloat16* __restrict__ A1g,
    const __nv_bfloat16* __restrict__ B0g, const __nv_bfloat16* __restrict__ B1g,
    uint32_t smem_u32, int st, int k0, int row0, int col0, int K, int tid)
{
    constexpr int A_STAGE = 2 * BM * KSTRIDE;
    constexpr int B_STAGE = 2 * BN * KSTRIDE;
    constexpr int B_BASE  = STAGES * A_STAGE;
    constexpr int TOT_A = BM * 8;           // 2 splits * BM rows * 4 chunks of 8 bf16
    constexpr int CPT = (BM + BN) * 8 / THREADS;
    #pragma unroll
    for (int t = 0; t < CPT; t++) {
        int i = tid + t * THREADS;
        if (i < TOT_A) {
            int sp = i / (BM * 4);
            int rr = (i >> 2) % BM;
            int kc = i & 3;
            const __nv_bfloat16* g = sp ? A1g : A0g;
            const __nv_bfloat16* src = g + (size_t)(row0 + rr) * K + k0 + kc * 8;
            uint32_t dst = smem_u32 + 2u * (uint32_t)(
                st * A_STAGE + (sp * BM + rr) * KSTRIDE + kc * 8);
            CP_ASYNC_CG16(dst, src);
        } else {
            int j = i - TOT_A;
            int sp = j / (BN * 4);
            int rr = (j >> 2) % BN;
            int kc = j & 3;
            const __nv_bfloat16* g = sp ? B1g : B0g;
            const __nv_bfloat16* src = g + (size_t)(col0 + rr) * K + k0 + kc * 8;
            uint32_t dst = smem_u32 + 2u * (uint32_t)(
                B_BASE + st * B_STAGE + (sp * BN + rr) * KSTRIDE + kc * 8);
            CP_ASYNC_CG16(dst, src);
        }
    }
}

template<int BM, int BN, int WM, int WN, int STAGES, int MODE>
__global__ void __launch_bounds__((BM / WM) * (BN / WN) * 32, 1)
mma_gemm_kernel(const __nv_bfloat16* __restrict__ A0g, const __nv_bfloat16* __restrict__ A1g,
                const __nv_bfloat16* __restrict__ B0g, const __nv_bfloat16* __restrict__ B1g,
                float* __restrict__ C, int N, int K,
                const float* __restrict__ rnA, const float* __restrict__ rnB,
                const float* __restrict__ Tm, const float* __restrict__ SHL)
{
    constexpr int THREADS = (BM / WM) * (BN / WN) * 32;
    constexpr int MB = WM / 16;
    constexpr int NB = WN / 8;
    constexpr int NB2 = WN / 16;
    constexpr int A_STAGE = 2 * BM * KSTRIDE;
    constexpr int B_STAGE = 2 * BN * KSTRIDE;
    constexpr int B_BASE  = STAGES * A_STAGE;
    constexpr int TILE_ELEMS = STAGES * (A_STAGE + B_STAGE);

    extern __shared__ char smem[];
    const uint32_t smem_u32 = smem_to_u32(smem);
    const int tid = threadIdx.x;
    const int wid = tid >> 5;
    const int lane = tid & 31;
    const int warps_n = BN / WN;
    const int wm0 = (wid / warps_n) * WM;
    const int wn0 = (wid % warps_n) * WN;
    const int row0 = blockIdx.y * BM;
    const int col0 = blockIdx.x * BN;

    float* sTm  = reinterpret_cast<float*>(smem + 2 * TILE_ELEMS);
    float* sShl = sTm + BM * NC;
    if (MODE == 2) {
        for (int i = tid; i < BM * NC; i += THREADS)
            sTm[i] = __ldg(&Tm[(size_t)(row0 + i / NC) * NC + (i % NC)]);
        for (int i = tid; i < BN * NC; i += THREADS)
            sShl[i] = __ldg(&SHL[(size_t)(col0 + i / NC) * NC + (i % NC)]);
    }

    float acc[MB][NB][4];
    #pragma unroll
    for (int i = 0; i < MB; i++)
        #pragma unroll
        for (int j = 0; j < NB; j++)
            #pragma unroll
            for (int q = 0; q < 4; q++) acc[i][j][q] = 0.f;

    const int nch = K >> 5;   // BK = 32
    #pragma unroll
    for (int s = 0; s < STAGES - 1; s++) {
        load_stage_fn<BM, BN, THREADS, STAGES>(A0g, A1g, B0g, B1g, smem_u32,
                                               s, s << 5, row0, col0, K, tid);
        CP_COMMIT();
    }

    const int lrow = lane & 15;
    const int lcol = (lane >> 4) << 3;

    for (int c = 0; c < nch; c++) {
        CP_WAIT(STAGES - 2);
        __syncthreads();
        int pf = c + STAGES - 1;
        if (pf < nch)
            load_stage_fn<BM, BN, THREADS, STAGES>(A0g, A1g, B0g, B1g, smem_u32,
                                                   pf % STAGES, pf << 5, row0, col0, K, tid);
        CP_COMMIT();
        const int st = c % STAGES;

        #pragma unroll
        for (int s16 = 0; s16 < 32; s16 += 16) {
            uint32_t Af[2][MB][4];
            uint32_t Bf[2][NB][2];
            #pragma unroll
            for (int sp = 0; sp < 2; sp++) {
                #pragma unroll
                for (int mb = 0; mb < MB; mb++) {
                    uint32_t addr = smem_u32 + 2u * (uint32_t)(
                        st * A_STAGE + (sp * BM + wm0 + mb * 16 + lrow) * KSTRIDE + s16 + lcol);
                    LDSM_X4(Af[sp][mb][0], Af[sp][mb][1], Af[sp][mb][2], Af[sp][mb][3], addr);
                }
                #pragma unroll
                for (int nb2 = 0; nb2 < NB2; nb2++) {
                    uint32_t r0, r1, r2, r3;
                    uint32_t addr = smem_u32 + 2u * (uint32_t)(
                        B_BASE + st * B_STAGE +
                        (sp * BN + wn0 + nb2 * 16 + lrow) * KSTRIDE + s16 + lcol);
                    LDSM_X4(r0, r1, r2, r3, addr);
                    Bf[sp][2 * nb2][0] = r0;     Bf[sp][2 * nb2][1] = r2;
                    Bf[sp][2 * nb2 + 1][0] = r1; Bf[sp][2 * nb2 + 1][1] = r3;
                }
            }
            #pragma unroll
            for (int mb = 0; mb < MB; mb++)
                #pragma unroll
                for (int nb = 0; nb < NB; nb++) {
                    MMA_16816(acc[mb][nb], Af[0][mb], Bf[0][nb]);
                    MMA_16816(acc[mb][nb], Af[0][mb], Bf[1][nb]);
                    MMA_16816(acc[mb][nb], Af[1][mb], Bf[0][nb]);
                }
        }
    }

    // ---------------- epilogue (direct from accumulator frags) ----------------
    const int lr = lane >> 2;
    const int lc = (lane & 3) * 2;
    #pragma unroll
    for (int mb = 0; mb < MB; mb++) {
        #pragma unroll
        for (int rr2 = 0; rr2 < 2; rr2++) {
            const int rg = row0 + wm0 + mb * 16 + lr + rr2 * 8;
            float ra = 0.f, tm[NC];
            if (MODE != 0) ra = __ldg(&rnA[rg]);
            if (MODE == 2) {
                #pragma unroll
                for (int cc = 0; cc < NC; cc++) tm[cc] = sTm[(rg - row0) * NC + cc];
            }
            #pragma unroll
            for (int nb = 0; nb < NB; nb++) {
                const int cg = col0 + wn0 + nb * 8 + lc;
                float v0 = acc[mb][nb][rr2 * 2];
                float v1 = acc[mb][nb][rr2 * 2 + 1];
                if (MODE != 0) {
                    float rb0 = __ldg(&rnB[cg]);
                    float rb1 = __ldg(&rnB[cg + 1]);
                    float d0 = sqrtf(fmaxf(ra + rb0 - 2.f * v0, 1e-12f));
                    float d1 = sqrtf(fmaxf(ra + rb1 - 2.f * v1, 1e-12f));
                    if (MODE == 2) {
                        float l0 = 0.f, l1 = 0.f;
                        #pragma unroll
                        for (int cc = 0; cc < NC; cc++) {
                            l0 = fmaf(tm[cc], sShl[(cg - col0) * NC + cc], l0);
                            l1 = fmaf(tm[cc], sShl[(cg + 1 - col0) * NC + cc], l1);
                        }
                        d0 += l0; d1 += l1;
                    }
                    v0 = -TEMP * d0; v1 = -TEMP * d1;
                }
                *reinterpret_cast<float2*>(&C[(size_t)rg * N + cg]) = make_float2(v0, v1);
            }
        }
    }
}

// ===================== fused row softmax + split2 (emits bf16 hi/lo weights) =====================
template<int NCOL, int THREADS>
__global__ void softmax_split_kernel(const float* __restrict__ X,
                                     __nv_bfloat16* __restrict__ W0,
                                     __nv_bfloat16* __restrict__ W1) {
    constexpr int PER = NCOL / THREADS;
    int row = blockIdx.x;
    const float* xr = X + (size_t)row * NCOL;
    int tid = threadIdx.x;
    float r[PER];
    float mx = -INFINITY;
    #pragma unroll
    for (int i = 0; i < PER; i++) {
        r[i] = xr[tid + i * THREADS];
        mx = fmaxf(mx, r[i]);
    }
    __shared__ float sred[THREADS / 32];
    #pragma unroll
    for (int o = 16; o > 0; o >>= 1) mx = fmaxf(mx, __shfl_xor_sync(0xffffffffu, mx, o));
    if ((tid & 31) == 0) sred[tid >> 5] = mx;
    __syncthreads();
    {
        float m = sred[0];
        #pragma unroll
        for (int i = 1; i < THREADS / 32; i++) m = fmaxf(m, sred[i]);
        mx = m;
    }
    __syncthreads();
    float s = 0.f;
    #pragma unroll
    for (int i = 0; i < PER; i++) {
        r[i] = expf(r[i] - mx);
        s += r[i];
    }
    #pragma unroll
    for (int o = 16; o > 0; o >>= 1) s += __shfl_xor_sync(0xffffffffu, s, o);
    if ((tid & 31) == 0) sred[tid >> 5] = s;
    __syncthreads();
    {
        float m = 0.f;
        #pragma unroll
        for (int i = 0; i < THREADS / 32; i++) m += sred[i];
        s = m;
    }
    float inv = 1.f / s;
    #pragma unroll
    for (int i = 0; i < PER; i++) {
        float wv = r[i] * inv;
        __nv_bfloat16 h, l;
        split2_one(wv, h, l);
        size_t o = (size_t)row * NCOL + tid + i * THREADS;
        W0[o] = h; W1[o] = l;
    }
}

// ===================== classifier head + x_src split-2 =====================
__global__ void preds_kernel(const float* __restrict__ xsrc, const float* __restrict__ W,
                             const float* __restrict__ b, const float* __restrict__ L,
                             float* __restrict__ t_out, float* __restrict__ xsn,
                             __nv_bfloat16* __restrict__ XS0, __nv_bfloat16* __restrict__ XS1)
{
    int row = blockIdx.x;
    int tid = threadIdx.x;
    const float* xr = xsrc + (size_t)row * DIM;
    float acc[NC];
    #pragma unroll
    for (int c = 0; c < NC; c++) acc[c] = 0.f;
    float nrm = 0.f;
    for (int k = tid; k < DIM; k += blockDim.x) {
        float xv = xr[k];
        nrm = fmaf(xv, xv, nrm);
        __nv_bfloat16 h, l;
        split2_one(xv, h, l);
        size_t o = (size_t)row * DIM + k;
        XS0[o] = h; XS1[o] = l;
        #pragma unroll
        for (int c = 0; c < NC; c++) acc[c] = fmaf(xv, __ldg(&W[k * NC + c]), acc[c]);
    }
    __shared__ float red[NC + 1][128];
    #pragma unroll
    for (int c = 0; c < NC; c++) red[c][tid] = acc[c];
    red[NC][tid] = nrm;
    __syncthreads();
    for (int st = 64; st > 0; st >>= 1) {
        if (tid < st) {
            #pragma unroll
            for (int c = 0; c <= NC; c++) red[c][tid] += red[c][tid + st];
        }
        __syncthreads();
    }
    if (tid == 0) {
        float lg[NC], m = -INFINITY, s = 0.f;
        #pragma unroll
        for (int c = 0; c < NC; c++) { lg[c] = red[c][0] + b[c]; m = fmaxf(m, lg[c]); }
        #pragma unroll
        for (int c = 0; c < NC; c++) { lg[c] = expf(lg[c] - m); s += lg[c]; }
        float inv = 1.f / s;
        #pragma unroll
        for (int c = 0; c < NC; c++) {
            float tv = 0.f;
            #pragma unroll
            for (int cc = 0; cc < NC; cc++) tv = fmaf(lg[cc] * inv, L[cc * NC + c], tv);
            t_out[row * NC + c] = tv;
        }
        xsn[row] = red[NC][0];
    }
}

// ===================== fused softmax + (w @ atl) =====================
__global__ void final_kernel(const float* __restrict__ logits, const float* __restrict__ atl,
                             float* __restrict__ y)
{
    constexpr int THREADS = 256;
    constexpr int PER = NS / THREADS;
    int row = blockIdx.x;
    int tid = threadIdx.x;
    const float* xr = logits + (size_t)row * NS;
    float r[PER];
    float mx = -INFINITY;
    #pragma unroll
    for (int i = 0; i < PER; i++) {
        r[i] = xr[tid + i * THREADS];
        mx = fmaxf(mx, r[i]);
    }
    __shared__ float sred[THREADS / 32];
    #pragma unroll
    for (int o = 16; o > 0; o >>= 1) mx = fmaxf(mx, __shfl_xor_sync(0xffffffffu, mx, o));
    if ((tid & 31) == 0) sred[tid >> 5] = mx;
    __syncthreads();
    {
        float m = sred[0];
        #pragma unroll
        for (int i = 1; i < THREADS / 32; i++) m = fmaxf(m, sred[i]);
        mx = m;
    }
    __syncthreads();

    float s = 0.f;
    float ya[NC];
    #pragma unroll
    for (int c = 0; c < NC; c++) ya[c] = 0.f;
    #pragma unroll
    for (int i = 0; i < PER; i++) {
        float e = expf(r[i] - mx);
        s += e;
        int j = tid + i * THREADS;
        const float* a = atl + (size_t)j * NC;
        #pragma unroll
        for (int c = 0; c < NC; c++) ya[c] = fmaf(e, __ldg(&a[c]), ya[c]);
    }
    __shared__ float red[NC + 1][THREADS];
    #pragma unroll
    for (int c = 0; c < NC; c++) red[c][tid] = ya[c];
    red[NC][tid] = s;
    __syncthreads();
    for (int st = THREADS / 2; st > 0; st >>= 1) {
        if (tid < st) {
            #pragma unroll
            for (int c = 0; c <= NC; c++) red[c][tid] += red[c][tid + st];
        }
        __syncthreads();
    }
    if (tid < NC) {
        y[row * NC + tid] = red[tid][0] / red[NC][0];
    }
}

// ===================== launch =====================
extern "C" void kernel_launch(void* const* d_in, const int* in_sizes, int n_in,
                              void* d_out, int out_size)
{
    const float* x   = (const float*)d_in[0];
    const float* tf  = (const float*)d_in[1];
    const float* asf = (const float*)d_in[2];
    const float* sf  = (const float*)d_in[3];
    const float* shl = (const float*)d_in[4];
    const float* atl = (const float*)d_in[5];
    const float* sld = (const float*)d_in[6];
    const float* W   = (const float*)d_in[7];
    const float* b   = (const float*)d_in[8];
    float* y = (float*)d_out;

    float *logits, *xsrc, *tn, *sn, *xn, *xsn, *tbuf;
    __nv_bfloat16 *x2, *tf2, *sf2, *asfT2, *w2, *xs2;
    cudaGetSymbolAddress((void**)&logits, g_logits);
    cudaGetSymbolAddress((void**)&xsrc,   g_xsrc);
    cudaGetSymbolAddress((void**)&tn,     g_tn);
    cudaGetSymbolAddress((void**)&sn,     g_sn);
    cudaGetSymbolAddress((void**)&xn,     g_xn);
    cudaGetSymbolAddress((void**)&xsn,    g_xsn);
    cudaGetSymbolAddress((void**)&tbuf,   g_t);
    cudaGetSymbolAddress((void**)&x2,     g_x2);
    cudaGetSymbolAddress((void**)&tf2,    g_tf2);
    cudaGetSymbolAddress((void**)&sf2,    g_sf2);
    cudaGetSymbolAddress((void**)&asfT2,  g_asfT2);
    cudaGetSymbolAddress((void**)&w2,     g_w2);
    cudaGetSymbolAddress((void**)&xs2,    g_xs2);

    // smem: tiles = 2B * STAGES * 2*(BM+BN) * KSTRIDE; + label region for MODE2
    const int smem_big   = 2 * 2 * 2 * (128 + 128) * KSTRIDE + 2 * 128 * NC * 4;  // 92160
    const int smem_g2    = 2 * 4 * 2 * (64 + 64) * KSTRIDE;                        // 81920
    cudaFuncSetAttribute(mma_gemm_kernel<128, 128, 64, 32, 2, 1>,
                         cudaFuncAttributeMaxDynamicSharedMemorySize, smem_big);
    cudaFuncSetAttribute(mma_gemm_kernel<128, 128, 64, 32, 2, 2>,
                         cudaFuncAttributeMaxDynamicSharedMemorySize, smem_big);
    cudaFuncSetAttribute(mma_gemm_kernel<64, 64, 64, 16, 4, 0>,
                         cudaFuncAttributeMaxDynamicSharedMemorySize, smem_g2);

    const size_t SZ_XD = (size_t)BATCH * DIM;
    const size_t SZ_TD = (size_t)NT * DIM;
    const size_t SZ_SD = (size_t)NS * DIM;
    const size_t SZ_DT = (size_t)DIM * NT;
    const size_t SZ_BN = (size_t)BATCH * NT;

    // 1) fused norm + split-2 (one pass per input)
    norm_split2_kernel<<<BATCH, 256>>>(x, x2, x2 + SZ_XD, xn);
    norm_split2_kernel<<<NT, 256>>>(tf, tf2, tf2 + SZ_TD, tn);
    norm_split2_kernel<<<NS, 256>>>(sf, sf2, sf2 + SZ_SD, sn);
    split2T_kernel<<<dim3(DIM / 32, NT / 32), dim3(32, 32)>>>(
        asf, asfT2, asfT2 + SZ_DT, NT, DIM);

    // 2) feature-transport logits: -T * cdist(xf, tf)   [1024 x 8192]
    mma_gemm_kernel<128, 128, 64, 32, 2, 1><<<dim3(NT / 128, BATCH / 128), 256, smem_big>>>(
        x2, x2 + SZ_XD, tf2, tf2 + SZ_TD, logits, NT, DIM, xn, tn, nullptr, nullptr);

    // 3) softmax over Nt, emitting split-2 bf16 weights directly
    softmax_split_kernel<NT, 256><<<BATCH, 256>>>(logits, w2, w2 + SZ_BN);

    // 4) x_src = w_feat @ asf   [1024 x 1024], K = 8192 — 4-stage pipeline, 64x16 warp tile
    mma_gemm_kernel<64, 64, 64, 16, 4, 0><<<dim3(DIM / 64, BATCH / 64), 128, smem_g2>>>(
        w2, w2 + SZ_BN, asfT2, asfT2 + SZ_DT, xsrc, DIM, NT,
        nullptr, nullptr, nullptr, nullptr);

    // 5) classifier head -> tbuf = preds @ L, ||x_src||^2, and x_src split-2
    preds_kernel<<<BATCH, 128>>>(xsrc, W, b, sld, tbuf, xsn, xs2, xs2 + SZ_XD);

    // 6) label-transport logits  [1024 x 8192]
    mma_gemm_kernel<128, 128, 64, 32, 2, 2><<<dim3(NS / 128, BATCH / 128), 256, smem_big>>>(
        xs2, xs2 + SZ_XD, sf2, sf2 + SZ_SD, logits, NS, DIM, xsn, sn, tbuf, shl);

    // 7) softmax over Ns fused with y = w_lab @ atl
    final_kernel<<<BATCH, 256>>>(logits, atl, y);
}

// round 10
// speedup vs baseline: 2.1741x; 1.0217x over previous
#include <cuda_runtime.h>
#include <cuda_bf16.h>
#include <math.h>
#include <stdint.h>

// ---------------- problem constants ----------------
#define BATCH 1024
#define NT    8192
#define NS    8192
#define DIM   1024
#define NC    10
#define TEMP  100.0f

// ---------------- scratch (device globals; no allocation) ----------------
__device__ float g_logits[(size_t)BATCH * NT];   // 32 MB
__device__ float g_xsrc[BATCH * DIM];
__device__ float g_tn[NT];
__device__ float g_sn[NS];
__device__ float g_xn[BATCH];
__device__ float g_xsn[BATCH];
__device__ float g_t[BATCH * NC];
__device__ float g_atlT[NC * NS];                // atl transposed [NC, NS]
// bf16 split-2 operand buffers (hi at offset 0, lo at offset SZ)
__device__ __nv_bfloat16 g_x2  [(size_t)2 * BATCH * DIM];
__device__ __nv_bfloat16 g_tf2 [(size_t)2 * NT * DIM];
__device__ __nv_bfloat16 g_sf2 [(size_t)2 * NS * DIM];
__device__ __nv_bfloat16 g_asfT2[(size_t)2 * DIM * NT];   // asf transposed: [DIM, NT]
__device__ __nv_bfloat16 g_w2  [(size_t)2 * BATCH * NT];
__device__ __nv_bfloat16 g_xs2 [(size_t)2 * BATCH * DIM];

// ===================== asm helpers (sm_80-era PTX; compiles for compute_103) =====================
__device__ __forceinline__ uint32_t smem_to_u32(const void* smem_ptr) {
    uint32_t addr;
    asm("{ .reg .u64 tmp; cvta.to.shared.u64 tmp, %1; cvt.u32.u64 %0, tmp; }"
        : "=r"(addr) : "l"(smem_ptr));
    return addr;
}
#define CP_ASYNC_CG16(dst, src) \
    asm volatile("cp.async.cg.shared.global [%0], [%1], 16;" :: "r"(dst), "l"(src))
#define CP_COMMIT() asm volatile("cp.async.commit_group;" ::: "memory")
#define CP_WAIT(n)  asm volatile("cp.async.wait_group %0;" :: "n"(n) : "memory")
#define LDSM_X4(r0, r1, r2, r3, addr) \
    asm volatile("ldmatrix.sync.aligned.m8n8.x4.shared.b16 {%0,%1,%2,%3}, [%4];" \
        : "=r"(r0), "=r"(r1), "=r"(r2), "=r"(r3) : "r"(addr))
#define MMA_16816(d, a, b) \
    asm volatile("mma.sync.aligned.m16n8k16.row.col.f32.bf16.bf16.f32 " \
        "{%0,%1,%2,%3}, {%4,%5,%6,%7}, {%8,%9}, {%0,%1,%2,%3};" \
        : "+f"((d)[0]), "+f"((d)[1]), "+f"((d)[2]), "+f"((d)[3]) \
        : "r"((a)[0]), "r"((a)[1]), "r"((a)[2]), "r"((a)[3]), \
          "r"((b)[0]), "r"((b)[1]))

// ===================== bf16 split-2 =====================
__device__ __forceinline__ void split2_one(float x, __nv_bfloat16& b0, __nv_bfloat16& b1) {
    b0 = __float2bfloat16(x);
    b1 = __float2bfloat16(x - __bfloat162float(b0));
}

// fused: row squared-norm + split-2 (one pass over X). X: [R, 1024]; 256 thr/row.
__global__ void norm_split2_kernel(const float* __restrict__ X,
                                   __nv_bfloat16* __restrict__ O0,
                                   __nv_bfloat16* __restrict__ O1,
                                   float* __restrict__ norms) {
    int row = blockIdx.x;
    int tid = threadIdx.x;
    const float* xr = X + (size_t)row * DIM;
    float4 v = *reinterpret_cast<const float4*>(xr + tid * 4);
    float s = v.x * v.x + v.y * v.y + v.z * v.z + v.w * v.w;
    __nv_bfloat16 a0, a1, b0, b1, c0, c1, d0, d1;
    split2_one(v.x, a0, a1);
    split2_one(v.y, b0, b1);
    split2_one(v.z, c0, c1);
    split2_one(v.w, d0, d1);
    size_t o = (size_t)row * DIM + tid * 4;
    *reinterpret_cast<__nv_bfloat162*>(O0 + o)     = __halves2bfloat162(a0, b0);
    *reinterpret_cast<__nv_bfloat162*>(O0 + o + 2) = __halves2bfloat162(c0, d0);
    *reinterpret_cast<__nv_bfloat162*>(O1 + o)     = __halves2bfloat162(a1, b1);
    *reinterpret_cast<__nv_bfloat162*>(O1 + o + 2) = __halves2bfloat162(c1, d1);
    #pragma unroll
    for (int off = 16; off > 0; off >>= 1) s += __shfl_xor_sync(0xffffffffu, s, off);
    __shared__ float ws[8];
    if ((tid & 31) == 0) ws[tid >> 5] = s;
    __syncthreads();
    if (tid == 0) {
        float t = 0.f;
        #pragma unroll
        for (int i = 0; i < 8; i++) t += ws[i];
        norms[row] = t;
    }
}

// transpose + split2: X [R, Cc] fp32 -> O* [Cc, R] bf16.  32x32 tiles, 256 threads.
// FIXED mapping: p = tx&15 (column pair), half = tx>>4; j = ty*2 + half + yy*16.
__global__ void split2T_kernel(const float* __restrict__ X,
                               __nv_bfloat16* __restrict__ O0,
                               __nv_bfloat16* __restrict__ O1, int R, int Cc) {
    __shared__ float t[32][33];
    int tx = threadIdx.x & 31;          // 0..31
    int ty = threadIdx.x >> 5;          // 0..7
    int r0 = blockIdx.y * 32;
    int c0 = blockIdx.x * 32;
    #pragma unroll
    for (int yy = 0; yy < 4; yy++) {
        int r = ty * 4 + yy;                       // 0..31, each exactly once
        t[r][tx] = X[(size_t)(r0 + r) * Cc + c0 + tx];
    }
    __syncthreads();
    int p = tx & 15;        // column-pair index 0..15  -> source rows p*2, p*2+1
    int half = tx >> 4;     // 0..1
    #pragma unroll
    for (int yy = 0; yy < 2; yy++) {
        int j = ty * 2 + half + yy * 16;           // output row within tile, 0..31 each once
        float v0 = t[p * 2][j], v1 = t[p * 2 + 1][j];
        __nv_bfloat16 h0, l0, h1, l1;
        split2_one(v0, h0, l0);
        split2_one(v1, h1, l1);
        size_t o = (size_t)(c0 + j) * R + r0 + p * 2;
        *reinterpret_cast<__nv_bfloat162*>(O0 + o) = __halves2bfloat162(h0, h1);
        *reinterpret_cast<__nv_bfloat162*>(O1 + o) = __halves2bfloat162(l0, l1);
    }
}

// tiny: atl [NS, NC] -> atlT [NC, NS]
__global__ void atlT_kernel(const float* __restrict__ atl, float* __restrict__ atlT) {
    int j = blockIdx.x * blockDim.x + threadIdx.x;
    if (j >= NS) return;
    #pragma unroll
    for (int c = 0; c < NC; c++) atlT[(size_t)c * NS + j] = atl[(size_t)j * NC + c];
}

// ===================== mma.sync bf16 split-2 GEMM =====================
// acc = A0*B0 + A0*B1 + A1*B0   (A = A0 + A1, B = B0 + B1; drop A1*B1)
// MODE 0: C = acc;  MODE 1: C = -T*sqrt(...);  MODE 2: MODE1 + label cost
#define KSTRIDE 40   // 32 used + 8 pad (bf16 elems) -> conflict-free ldmatrix

template<int BM, int BN, int THREADS, int STAGES>
__device__ __forceinline__ void load_stage_fn(
    const __nv_bfloat16* __restrict__ A0g, const __nv_bfloat16* __restrict__ A1g,
    const __nv_bfloat16* __restrict__ B0g, const __nv_bfloat16* __restrict__ B1g,
    uint32_t smem_u32, int st, int k0, int row0, int col0, int K, int tid)
{
    constexpr int A_STAGE = 2 * BM * KSTRIDE;
    constexpr int B_STAGE = 2 * BN * KSTRIDE;
    constexpr int B_BASE  = STAGES * A_STAGE;
    constexpr int TOT_A = BM * 8;
    constexpr int CPT = (BM + BN) * 8 / THREADS;
    #pragma unroll
    for (int t = 0; t < CPT; t++) {
        int i = tid + t * THREADS;
        if (i < TOT_A) {
            int sp = i / (BM * 4);
            int rr = (i >> 2) % BM;
            int kc = i & 3;
            const __nv_bfloat16* g = sp ? A1g : A0g;
            const __nv_bfloat16* src = g + (size_t)(row0 + rr) * K + k0 + kc * 8;
            uint32_t dst = smem_u32 + 2u * (uint32_t)(
                st * A_STAGE + (sp * BM + rr) * KSTRIDE + kc * 8);
            CP_ASYNC_CG16(dst, src);
        } else {
            int j = i - TOT_A;
            int sp = j / (BN * 4);
            int rr = (j >> 2) % BN;
            int kc = j & 3;
            const __nv_bfloat16* g = sp ? B1g : B0g;
            const __nv_bfloat16* src = g + (size_t)(col0 + rr) * K + k0 + kc * 8;
            uint32_t dst = smem_u32 + 2u * (uint32_t)(
                B_BASE + st * B_STAGE + (sp * BN + rr) * KSTRIDE + kc * 8);
            CP_ASYNC_CG16(dst, src);
        }
    }
}

template<int BM, int BN, int WM, int WN, int STAGES, int MODE>
__global__ void __launch_bounds__((BM / WM) * (BN / WN) * 32, 1)
mma_gemm_kernel(const __nv_bfloat16* __restrict__ A0g, const __nv_bfloat16* __restrict__ A1g,
                const __nv_bfloat16* __restrict__ B0g, const __nv_bfloat16* __restrict__ B1g,
                float* __restrict__ C, int N, int K,
                const float* __restrict__ rnA, const float* __restrict__ rnB,
                const float* __restrict__ Tm, const float* __restrict__ SHL)
{
    constexpr int THREADS = (BM / WM) * (BN / WN) * 32;
    constexpr int MB = WM / 16;
    constexpr int NB = WN / 8;
    constexpr int NB2 = WN / 16;
    constexpr int A_STAGE = 2 * BM * KSTRIDE;
    constexpr int B_STAGE = 2 * BN * KSTRIDE;
    constexpr int B_BASE  = STAGES * A_STAGE;
    constexpr int TILE_ELEMS = STAGES * (A_STAGE + B_STAGE);

    extern __shared__ char smem[];
    const uint32_t smem_u32 = smem_to_u32(smem);
    const int tid = threadIdx.x;
    const int wid = tid >> 5;
    const int lane = tid & 31;
    const int warps_n = BN / WN;
    const int wm0 = (wid / warps_n) * WM;
    const int wn0 = (wid % warps_n) * WN;
    const int row0 = blockIdx.y * BM;
    const int col0 = blockIdx.x * BN;

    float* sTm  = reinterpret_cast<float*>(smem + 2 * TILE_ELEMS);
    float* sShl = sTm + BM * NC;
    if (MODE == 2) {
        for (int i = tid; i < BM * NC; i += THREADS)
            sTm[i] = __ldg(&Tm[(size_t)(row0 + i / NC) * NC + (i % NC)]);
        for (int i = tid; i < BN * NC; i += THREADS)
            sShl[i] = __ldg(&SHL[(size_t)(col0 + i / NC) * NC + (i % NC)]);
    }

    float acc[MB][NB][4];
    #pragma unroll
    for (int i = 0; i < MB; i++)
        #pragma unroll
        for (int j = 0; j < NB; j++)
            #pragma unroll
            for (int q = 0; q < 4; q++) acc[i][j][q] = 0.f;

    const int nch = K >> 5;   // BK = 32
    #pragma unroll
    for (int s = 0; s < STAGES - 1; s++) {
        load_stage_fn<BM, BN, THREADS, STAGES>(A0g, A1g, B0g, B1g, smem_u32,
                                               s, s << 5, row0, col0, K, tid);
        CP_COMMIT();
    }

    const int lrow = lane & 15;
    const int lcol = (lane >> 4) << 3;

    for (int c = 0; c < nch; c++) {
        CP_WAIT(STAGES - 2);
        __syncthreads();
        int pf = c + STAGES - 1;
        if (pf < nch)
            load_stage_fn<BM, BN, THREADS, STAGES>(A0g, A1g, B0g, B1g, smem_u32,
                                                   pf % STAGES, pf << 5, row0, col0, K, tid);
        CP_COMMIT();
        const int st = c % STAGES;

        #pragma unroll
        for (int s16 = 0; s16 < 32; s16 += 16) {
            uint32_t Af[2][MB][4];
            uint32_t Bf[2][NB][2];
            #pragma unroll
            for (int sp = 0; sp < 2; sp++) {
                #pragma unroll
                for (int mb = 0; mb < MB; mb++) {
                    uint32_t addr = smem_u32 + 2u * (uint32_t)(
                        st * A_STAGE + (sp * BM + wm0 + mb * 16 + lrow) * KSTRIDE + s16 + lcol);
                    LDSM_X4(Af[sp][mb][0], Af[sp][mb][1], Af[sp][mb][2], Af[sp][mb][3], addr);
                }
                #pragma unroll
                for (int nb2 = 0; nb2 < NB2; nb2++) {
                    uint32_t r0, r1, r2, r3;
                    uint32_t addr = smem_u32 + 2u * (uint32_t)(
                        B_BASE + st * B_STAGE +
                        (sp * BN + wn0 + nb2 * 16 + lrow) * KSTRIDE + s16 + lcol);
                    LDSM_X4(r0, r1, r2, r3, addr);
                    Bf[sp][2 * nb2][0] = r0;     Bf[sp][2 * nb2][1] = r2;
                    Bf[sp][2 * nb2 + 1][0] = r1; Bf[sp][2 * nb2 + 1][1] = r3;
                }
            }
            #pragma unroll
            for (int mb = 0; mb < MB; mb++)
                #pragma unroll
                for (int nb = 0; nb < NB; nb++) {
                    MMA_16816(acc[mb][nb], Af[0][mb], Bf[0][nb]);
                    MMA_16816(acc[mb][nb], Af[0][mb], Bf[1][nb]);
                    MMA_16816(acc[mb][nb], Af[1][mb], Bf[0][nb]);
                }
        }
    }

    // ---------------- epilogue ----------------
    const int lr = lane >> 2;
    const int lc = (lane & 3) * 2;
    #pragma unroll
    for (int mb = 0; mb < MB; mb++) {
        #pragma unroll
        for (int rr2 = 0; rr2 < 2; rr2++) {
            const int rg = row0 + wm0 + mb * 16 + lr + rr2 * 8;
            float ra = 0.f, tm[NC];
            if (MODE != 0) ra = __ldg(&rnA[rg]);
            if (MODE == 2) {
                #pragma unroll
                for (int cc = 0; cc < NC; cc++) tm[cc] = sTm[(rg - row0) * NC + cc];
            }
            #pragma unroll
            for (int nb = 0; nb < NB; nb++) {
                const int cg = col0 + wn0 + nb * 8 + lc;
                float v0 = acc[mb][nb][rr2 * 2];
                float v1 = acc[mb][nb][rr2 * 2 + 1];
                if (MODE != 0) {
                    float rb0 = __ldg(&rnB[cg]);
                    float rb1 = __ldg(&rnB[cg + 1]);
                    float d0 = sqrtf(fmaxf(ra + rb0 - 2.f * v0, 1e-12f));
                    float d1 = sqrtf(fmaxf(ra + rb1 - 2.f * v1, 1e-12f));
                    if (MODE == 2) {
                        float l0 = 0.f, l1 = 0.f;
                        #pragma unroll
                        for (int cc = 0; cc < NC; cc++) {
                            l0 = fmaf(tm[cc], sShl[(cg - col0) * NC + cc], l0);
                            l1 = fmaf(tm[cc], sShl[(cg + 1 - col0) * NC + cc], l1);
                        }
                        d0 += l0; d1 += l1;
                    }
                    v0 = -TEMP * d0; v1 = -TEMP * d1;
                }
                *reinterpret_cast<float2*>(&C[(size_t)rg * N + cg]) = make_float2(v0, v1);
            }
        }
    }
}

// ===================== fused row softmax + split2 (bf16 hi/lo weights) =====================
template<int NCOL, int THREADS>
__global__ void softmax_split_kernel(const float* __restrict__ X,
                                     __nv_bfloat16* __restrict__ W0,
                                     __nv_bfloat16* __restrict__ W1) {
    constexpr int PER = NCOL / THREADS;
    int row = blockIdx.x;
    const float* xr = X + (size_t)row * NCOL;
    int tid = threadIdx.x;
    float r[PER];
    float mx = -INFINITY;
    #pragma unroll
    for (int i = 0; i < PER; i++) {
        r[i] = xr[tid + i * THREADS];
        mx = fmaxf(mx, r[i]);
    }
    __shared__ float sred[THREADS / 32];
    #pragma unroll
    for (int o = 16; o > 0; o >>= 1) mx = fmaxf(mx, __shfl_xor_sync(0xffffffffu, mx, o));
    if ((tid & 31) == 0) sred[tid >> 5] = mx;
    __syncthreads();
    {
        float m = sred[0];
        #pragma unroll
        for (int i = 1; i < THREADS / 32; i++) m = fmaxf(m, sred[i]);
        mx = m;
    }
    __syncthreads();
    float s = 0.f;
    #pragma unroll
    for (int i = 0; i < PER; i++) {
        r[i] = expf(r[i] - mx);
        s += r[i];
    }
    #pragma unroll
    for (int o = 16; o > 0; o >>= 1) s += __shfl_xor_sync(0xffffffffu, s, o);
    if ((tid & 31) == 0) sred[tid >> 5] = s;
    __syncthreads();
    {
        float m = 0.f;
        #pragma unroll
        for (int i = 0; i < THREADS / 32; i++) m += sred[i];
        s = m;
    }
    float inv = 1.f / s;
    #pragma unroll
    for (int i = 0; i < PER; i++) {
        float wv = r[i] * inv;
        __nv_bfloat16 h, l;
        split2_one(wv, h, l);
        size_t o = (size_t)row * NCOL + tid + i * THREADS;
        W0[o] = h; W1[o] = l;
    }
}

// ===================== classifier head + x_src split-2 =====================
__global__ void preds_kernel(const float* __restrict__ xsrc, const float* __restrict__ W,
                             const float* __restrict__ b, const float* __restrict__ L,
                             float* __restrict__ t_out, float* __restrict__ xsn,
                             __nv_bfloat16* __restrict__ XS0, __nv_bfloat16* __restrict__ XS1)
{
    int row = blockIdx.x;
    int tid = threadIdx.x;
    const float* xr = xsrc + (size_t)row * DIM;
    float acc[NC];
    #pragma unroll
    for (int c = 0; c < NC; c++) acc[c] = 0.f;
    float nrm = 0.f;
    for (int k = tid; k < DIM; k += blockDim.x) {
        float xv = xr[k];
        nrm = fmaf(xv, xv, nrm);
        __nv_bfloat16 h, l;
        split2_one(xv, h, l);
        size_t o = (size_t)row * DIM + k;
        XS0[o] = h; XS1[o] = l;
        #pragma unroll
        for (int c = 0; c < NC; c++) acc[c] = fmaf(xv, __ldg(&W[k * NC + c]), acc[c]);
    }
    __shared__ float red[NC + 1][128];
    #pragma unroll
    for (int c = 0; c < NC; c++) red[c][tid] = acc[c];
    red[NC][tid] = nrm;
    __syncthreads();
    for (int st = 64; st > 0; st >>= 1) {
        if (tid < st) {
            #pragma unroll
            for (int c = 0; c <= NC; c++) red[c][tid] += red[c][tid + st];
        }
        __syncthreads();
    }
    if (tid == 0) {
        float lg[NC], m = -INFINITY, s = 0.f;
        #pragma unroll
        for (int c = 0; c < NC; c++) { lg[c] = red[c][0] + b[c]; m = fmaxf(m, lg[c]); }
        #pragma unroll
        for (int c = 0; c < NC; c++) { lg[c] = expf(lg[c] - m); s += lg[c]; }
        float inv = 1.f / s;
        #pragma unroll
        for (int c = 0; c < NC; c++) {
            float tv = 0.f;
            #pragma unroll
            for (int cc = 0; cc < NC; cc++) tv = fmaf(lg[cc] * inv, L[cc * NC + c], tv);
            t_out[row * NC + c] = tv;
        }
        xsn[row] = red[NC][0];
    }
}

// ===================== fused softmax + (w @ atlT) =====================
__global__ void final_kernel(const float* __restrict__ logits, const float* __restrict__ atlT,
                             float* __restrict__ y)
{
    constexpr int THREADS = 512;
    constexpr int PER = NS / THREADS;   // 16
    int row = blockIdx.x;
    int tid = threadIdx.x;
    const float* xr = logits + (size_t)row * NS;
    float r[PER];
    float mx = -INFINITY;
    #pragma unroll
    for (int i = 0; i < PER; i++) {
        r[i] = xr[tid + i * THREADS];
        mx = fmaxf(mx, r[i]);
    }
    __shared__ float sred[THREADS / 32];
    #pragma unroll
    for (int o = 16; o > 0; o >>= 1) mx = fmaxf(mx, __shfl_xor_sync(0xffffffffu, mx, o));
    if ((tid & 31) == 0) sred[tid >> 5] = mx;
    __syncthreads();
    {
        float m = sred[0];
        #pragma unroll
        for (int i = 1; i < THREADS / 32; i++) m = fmaxf(m, sred[i]);
        mx = m;
    }
    __syncthreads();

    float s = 0.f;
    float e[PER];
    #pragma unroll
    for (int i = 0; i < PER; i++) {
        e[i] = expf(r[i] - mx);
        s += e[i];
    }
    float ya[NC];
    #pragma unroll
    for (int c = 0; c < NC; c++) {
        float a = 0.f;
        #pragma unroll
        for (int i = 0; i < PER; i++)
            a = fmaf(e[i], __ldg(&atlT[(size_t)c * NS + tid + i * THREADS]), a);
        ya[c] = a;
    }
    __shared__ float red[NC + 1][THREADS];
    #pragma unroll
    for (int c = 0; c < NC; c++) red[c][tid] = ya[c];
    red[NC][tid] = s;
    __syncthreads();
    for (int st = THREADS / 2; st > 0; st >>= 1) {
        if (tid < st) {
            #pragma unroll
            for (int c = 0; c <= NC; c++) red[c][tid] += red[c][tid + st];
        }
        __syncthreads();
    }
    if (tid < NC) {
        y[row * NC + tid] = red[tid][0] / red[NC][0];
    }
}

// ===================== launch =====================
extern "C" void kernel_launch(void* const* d_in, const int* in_sizes, int n_in,
                              void* d_out, int out_size)
{
    const float* x   = (const float*)d_in[0];
    const float* tf  = (const float*)d_in[1];
    const float* asf = (const float*)d_in[2];
    const float* sf  = (const float*)d_in[3];
    const float* shl = (const float*)d_in[4];
    const float* atl = (const float*)d_in[5];
    const float* sld = (const float*)d_in[6];
    const float* W   = (const float*)d_in[7];
    const float* b   = (const float*)d_in[8];
    float* y = (float*)d_out;

    float *logits, *xsrc, *tn, *sn, *xn, *xsn, *tbuf, *atlT;
    __nv_bfloat16 *x2, *tf2, *sf2, *asfT2, *w2, *xs2;
    cudaGetSymbolAddress((void**)&logits, g_logits);
    cudaGetSymbolAddress((void**)&xsrc,   g_xsrc);
    cudaGetSymbolAddress((void**)&tn,     g_tn);
    cudaGetSymbolAddress((void**)&sn,     g_sn);
    cudaGetSymbolAddress((void**)&xn,     g_xn);
    cudaGetSymbolAddress((void**)&xsn,    g_xsn);
    cudaGetSymbolAddress((void**)&tbuf,   g_t);
    cudaGetSymbolAddress((void**)&atlT,   g_atlT);
    cudaGetSymbolAddress((void**)&x2,     g_x2);
    cudaGetSymbolAddress((void**)&tf2,    g_tf2);
    cudaGetSymbolAddress((void**)&sf2,    g_sf2);
    cudaGetSymbolAddress((void**)&asfT2,  g_asfT2);
    cudaGetSymbolAddress((void**)&w2,     g_w2);
    cudaGetSymbolAddress((void**)&xs2,    g_xs2);

    // smem: tiles = 2B * STAGES * 2*(BM+BN) * KSTRIDE; + label region
    const int smem_big = 2 * 3 * 2 * (128 + 128) * KSTRIDE + 2 * 128 * NC * 4;  // 133120
    const int smem_g2  = 2 * 4 * 2 * (64 + 64) * KSTRIDE;                        // 81920
    cudaFuncSetAttribute(mma_gemm_kernel<128, 128, 64, 32, 3, 1>,
                         cudaFuncAttributeMaxDynamicSharedMemorySize, smem_big);
    cudaFuncSetAttribute(mma_gemm_kernel<128, 128, 64, 32, 3, 2>,
                         cudaFuncAttributeMaxDynamicSharedMemorySize, smem_big);
    cudaFuncSetAttribute(mma_gemm_kernel<64, 64, 64, 16, 4, 0>,
                         cudaFuncAttributeMaxDynamicSharedMemorySize, smem_g2);

    const size_t SZ_XD = (size_t)BATCH * DIM;
    const size_t SZ_TD = (size_t)NT * DIM;
    const size_t SZ_SD = (size_t)NS * DIM;
    const size_t SZ_DT = (size_t)DIM * NT;
    const size_t SZ_BN = (size_t)BATCH * NT;

    // 1) fused norm + split-2 (one pass per input) + transposes
    norm_split2_kernel<<<BATCH, 256>>>(x, x2, x2 + SZ_XD, xn);
    norm_split2_kernel<<<NT, 256>>>(tf, tf2, tf2 + SZ_TD, tn);
    norm_split2_kernel<<<NS, 256>>>(sf, sf2, sf2 + SZ_SD, sn);
    split2T_kernel<<<dim3(DIM / 32, NT / 32), 256>>>(asf, asfT2, asfT2 + SZ_DT, NT, DIM);
    atlT_kernel<<<NS / 256, 256>>>(atl, atlT);

    // 2) feature-transport logits: -T * cdist(xf, tf)   [1024 x 8192]
    mma_gemm_kernel<128, 128, 64, 32, 3, 1><<<dim3(NT / 128, BATCH / 128), 256, smem_big>>>(
        x2, x2 + SZ_XD, tf2, tf2 + SZ_TD, logits, NT, DIM, xn, tn, nullptr, nullptr);

    // 3) softmax over Nt, emitting split-2 bf16 weights directly
    softmax_split_kernel<NT, 512><<<BATCH, 512>>>(logits, w2, w2 + SZ_BN);

    // 4) x_src = w_feat @ asf   [1024 x 1024], K = 8192
    mma_gemm_kernel<64, 64, 64, 16, 4, 0><<<dim3(DIM / 64, BATCH / 64), 128, smem_g2>>>(
        w2, w2 + SZ_BN, asfT2, asfT2 + SZ_DT, xsrc, DIM, NT,
        nullptr, nullptr, nullptr, nullptr);

    // 5) classifier head -> tbuf = preds @ L, ||x_src||^2, and x_src split-2
    preds_kernel<<<BATCH, 128>>>(xsrc, W, b, sld, tbuf, xsn, xs2, xs2 + SZ_XD);

    // 6) label-transport logits  [1024 x 8192]
    mma_gemm_kernel<128, 128, 64, 32, 3, 2><<<dim3(NS / 128, BATCH / 128), 256, smem_big>>>(
        xs2, xs2 + SZ_XD, sf2, sf2 + SZ_SD, logits, NS, DIM, xsn, sn, tbuf, shl);

    // 7) softmax over Ns fused with y = w_lab @ atlT
    final_kernel<<<BATCH, 512>>>(logits, atlT, y);
}

// round 11
// speedup vs baseline: 2.1936x; 1.0090x over previous
#include <cuda_runtime.h>
#include <cuda_fp16.h>
#include <math.h>
#include <stdint.h>

// ---------------- problem constants ----------------
#define BATCH 1024
#define NT    8192
#define NS    8192
#define DIM   1024
#define NC    10
#define TEMP  100.0f

// ---------------- scratch (device globals; no allocation) ----------------
__device__ float g_logits[(size_t)BATCH * NT];   // 32 MB
__device__ float g_xsrc[BATCH * DIM];
__device__ float g_tn[NT];
__device__ float g_sn[NS];
__device__ float g_xn[BATCH];
__device__ float g_xsn[BATCH];
__device__ float g_t[BATCH * NC];
__device__ float g_atlT[NC * NS];                // atl transposed [NC, NS]
// fp16 split-2 operand buffers (hi at offset 0, lo at offset SZ)
__device__ __half g_x2  [(size_t)2 * BATCH * DIM];
__device__ __half g_tf2 [(size_t)2 * NT * DIM];
__device__ __half g_sf2 [(size_t)2 * NS * DIM];
__device__ __half g_asfT2[(size_t)2 * DIM * NT];   // asf transposed: [DIM, NT]
__device__ __half g_w2  [(size_t)2 * BATCH * NT];
__device__ __half g_xs2 [(size_t)2 * BATCH * DIM];

// ===================== asm helpers (sm_80-era PTX; compiles for compute_103) =====================
__device__ __forceinline__ uint32_t smem_to_u32(const void* smem_ptr) {
    uint32_t addr;
    asm("{ .reg .u64 tmp; cvta.to.shared.u64 tmp, %1; cvt.u32.u64 %0, tmp; }"
        : "=r"(addr) : "l"(smem_ptr));
    return addr;
}
#define CP_ASYNC_CG16(dst, src) \
    asm volatile("cp.async.cg.shared.global [%0], [%1], 16;" :: "r"(dst), "l"(src))
#define CP_COMMIT() asm volatile("cp.async.commit_group;" ::: "memory")
#define CP_WAIT(n)  asm volatile("cp.async.wait_group %0;" :: "n"(n) : "memory")
#define LDSM_X4(r0, r1, r2, r3, addr) \
    asm volatile("ldmatrix.sync.aligned.m8n8.x4.shared.b16 {%0,%1,%2,%3}, [%4];" \
        : "=r"(r0), "=r"(r1), "=r"(r2), "=r"(r3) : "r"(addr))
#define MMA_16816(d, a, b) \
    asm volatile("mma.sync.aligned.m16n8k16.row.col.f32.f16.f16.f32 " \
        "{%0,%1,%2,%3}, {%4,%5,%6,%7}, {%8,%9}, {%0,%1,%2,%3};" \
        : "+f"((d)[0]), "+f"((d)[1]), "+f"((d)[2]), "+f"((d)[3]) \
        : "r"((a)[0]), "r"((a)[1]), "r"((a)[2]), "r"((a)[3]), \
          "r"((b)[0]), "r"((b)[1]))

// ===================== fp16 split-2 =====================
__device__ __forceinline__ void split2_one(float x, __half& h0, __half& h1) {
    h0 = __float2half_rn(x);
    h1 = __float2half_rn(x - __half2float(h0));
}

// fused: row squared-norm + split-2 (one pass over X). X: [R, 1024]; 256 thr/row.
__global__ void norm_split2_kernel(const float* __restrict__ X,
                                   __half* __restrict__ O0,
                                   __half* __restrict__ O1,
                                   float* __restrict__ norms) {
    int row = blockIdx.x;
    int tid = threadIdx.x;
    const float* xr = X + (size_t)row * DIM;
    float4 v = *reinterpret_cast<const float4*>(xr + tid * 4);
    float s = v.x * v.x + v.y * v.y + v.z * v.z + v.w * v.w;
    __half a0, a1, b0, b1, c0, c1, d0, d1;
    split2_one(v.x, a0, a1);
    split2_one(v.y, b0, b1);
    split2_one(v.z, c0, c1);
    split2_one(v.w, d0, d1);
    size_t o = (size_t)row * DIM + tid * 4;
    *reinterpret_cast<__half2*>(O0 + o)     = __halves2half2(a0, b0);
    *reinterpret_cast<__half2*>(O0 + o + 2) = __halves2half2(c0, d0);
    *reinterpret_cast<__half2*>(O1 + o)     = __halves2half2(a1, b1);
    *reinterpret_cast<__half2*>(O1 + o + 2) = __halves2half2(c1, d1);
    #pragma unroll
    for (int off = 16; off > 0; off >>= 1) s += __shfl_xor_sync(0xffffffffu, s, off);
    __shared__ float ws[8];
    if ((tid & 31) == 0) ws[tid >> 5] = s;
    __syncthreads();
    if (tid == 0) {
        float t = 0.f;
        #pragma unroll
        for (int i = 0; i < 8; i++) t += ws[i];
        norms[row] = t;
    }
}

// transpose + split2: X [R, Cc] fp32 -> O* [Cc, R] fp16.  32x32 tiles, 256 threads.
__global__ void split2T_kernel(const float* __restrict__ X,
                               __half* __restrict__ O0,
                               __half* __restrict__ O1, int R, int Cc) {
    __shared__ float t[32][33];
    int tx = threadIdx.x & 31;          // 0..31
    int ty = threadIdx.x >> 5;          // 0..7
    int r0 = blockIdx.y * 32;
    int c0 = blockIdx.x * 32;
    #pragma unroll
    for (int yy = 0; yy < 4; yy++) {
        int r = ty * 4 + yy;
        t[r][tx] = X[(size_t)(r0 + r) * Cc + c0 + tx];
    }
    __syncthreads();
    int p = tx & 15;
    int half = tx >> 4;
    #pragma unroll
    for (int yy = 0; yy < 2; yy++) {
        int j = ty * 2 + half + yy * 16;
        float v0 = t[p * 2][j], v1 = t[p * 2 + 1][j];
        __half h0, l0, h1, l1;
        split2_one(v0, h0, l0);
        split2_one(v1, h1, l1);
        size_t o = (size_t)(c0 + j) * R + r0 + p * 2;
        *reinterpret_cast<__half2*>(O0 + o) = __halves2half2(h0, h1);
        *reinterpret_cast<__half2*>(O1 + o) = __halves2half2(l0, l1);
    }
}

// tiny: atl [NS, NC] -> atlT [NC, NS]
__global__ void atlT_kernel(const float* __restrict__ atl, float* __restrict__ atlT) {
    int j = blockIdx.x * blockDim.x + threadIdx.x;
    if (j >= NS) return;
    #pragma unroll
    for (int c = 0; c < NC; c++) atlT[(size_t)c * NS + j] = atl[(size_t)j * NC + c];
}

// ===================== mma.sync fp16 split-2 GEMM =====================
// acc = A0*B0 + A0*B1 + A1*B0   (A = A0 + A1, B = B0 + B1; drop A1*B1)
// MODE 0: C = acc;  MODE 1: C = -T*sqrt(...);  MODE 2: MODE1 + label cost
#define KSTRIDE 40   // 32 used + 8 pad (fp16 elems) -> conflict-free ldmatrix

template<int BM, int BN, int THREADS, int STAGES>
__device__ __forceinline__ void load_stage_fn(
    const __half* __restrict__ A0g, const __half* __restrict__ A1g,
    const __half* __restrict__ B0g, const __half* __restrict__ B1g,
    uint32_t smem_u32, int st, int k0, int row0, int col0, int K, int tid)
{
    constexpr int A_STAGE = 2 * BM * KSTRIDE;
    constexpr int B_STAGE = 2 * BN * KSTRIDE;
    constexpr int B_BASE  = STAGES * A_STAGE;
    constexpr int TOT_A = BM * 8;
    constexpr int CPT = (BM + BN) * 8 / THREADS;
    #pragma unroll
    for (int t = 0; t < CPT; t++) {
        int i = tid + t * THREADS;
        if (i < TOT_A) {
            int sp = i / (BM * 4);
            int rr = (i >> 2) % BM;
            int kc = i & 3;
            const __half* g = sp ? A1g : A0g;
            const __half* src = g + (size_t)(row0 + rr) * K + k0 + kc * 8;
            uint32_t dst = smem_u32 + 2u * (uint32_t)(
                st * A_STAGE + (sp * BM + rr) * KSTRIDE + kc * 8);
            CP_ASYNC_CG16(dst, src);
        } else {
            int j = i - TOT_A;
            int sp = j / (BN * 4);
            int rr = (j >> 2) % BN;
            int kc = j & 3;
            const __half* g = sp ? B1g : B0g;
            const __half* src = g + (size_t)(col0 + rr) * K + k0 + kc * 8;
            uint32_t dst = smem_u32 + 2u * (uint32_t)(
                B_BASE + st * B_STAGE + (sp * BN + rr) * KSTRIDE + kc * 8);
            CP_ASYNC_CG16(dst, src);
        }
    }
}

template<int BM, int BN, int WM, int WN, int STAGES, int MODE>
__global__ void __launch_bounds__((BM / WM) * (BN / WN) * 32, 1)
mma_gemm_kernel(const __half* __restrict__ A0g, const __half* __restrict__ A1g,
                const __half* __restrict__ B0g, const __half* __restrict__ B1g,
                float* __restrict__ C, int N, int K,
                const float* __restrict__ rnA, const float* __restrict__ rnB,
                const float* __restrict__ Tm, const float* __restrict__ SHL)
{
    constexpr int THREADS = (BM / WM) * (BN / WN) * 32;
    constexpr int MB = WM / 16;
    constexpr int NB = WN / 8;
    constexpr int NB2 = WN / 16;
    constexpr int A_STAGE = 2 * BM * KSTRIDE;
    constexpr int B_STAGE = 2 * BN * KSTRIDE;
    constexpr int B_BASE  = STAGES * A_STAGE;
    constexpr int TILE_ELEMS = STAGES * (A_STAGE + B_STAGE);

    extern __shared__ char smem[];
    const uint32_t smem_u32 = smem_to_u32(smem);
    const int tid = threadIdx.x;
    const int wid = tid >> 5;
    const int lane = tid & 31;
    const int warps_n = BN / WN;
    const int wm0 = (wid / warps_n) * WM;
    const int wn0 = (wid % warps_n) * WN;
    const int row0 = blockIdx.y * BM;
    const int col0 = blockIdx.x * BN;

    float* sTm  = reinterpret_cast<float*>(smem + 2 * TILE_ELEMS);
    float* sShl = sTm + BM * NC;
    if (MODE == 2) {
        for (int i = tid; i < BM * NC; i += THREADS)
            sTm[i] = __ldg(&Tm[(size_t)(row0 + i / NC) * NC + (i % NC)]);
        for (int i = tid; i < BN * NC; i += THREADS)
            sShl[i] = __ldg(&SHL[(size_t)(col0 + i / NC) * NC + (i % NC)]);
    }

    float acc[MB][NB][4];
    #pragma unroll
    for (int i = 0; i < MB; i++)
        #pragma unroll
        for (int j = 0; j < NB; j++)
            #pragma unroll
            for (int q = 0; q < 4; q++) acc[i][j][q] = 0.f;

    const int nch = K >> 5;   // BK = 32
    #pragma unroll
    for (int s = 0; s < STAGES - 1; s++) {
        load_stage_fn<BM, BN, THREADS, STAGES>(A0g, A1g, B0g, B1g, smem_u32,
                                               s, s << 5, row0, col0, K, tid);
        CP_COMMIT();
    }

    const int lrow = lane & 15;
    const int lcol = (lane >> 4) << 3;

    for (int c = 0; c < nch; c++) {
        CP_WAIT(STAGES - 2);
        __syncthreads();
        int pf = c + STAGES - 1;
        if (pf < nch)
            load_stage_fn<BM, BN, THREADS, STAGES>(A0g, A1g, B0g, B1g, smem_u32,
                                                   pf % STAGES, pf << 5, row0, col0, K, tid);
        CP_COMMIT();
        const int st = c % STAGES;

        #pragma unroll
        for (int s16 = 0; s16 < 32; s16 += 16) {
            // A fragments for both splits (live across whole s16 step)
            uint32_t Af[2][MB][4];
            #pragma unroll
            for (int sp = 0; sp < 2; sp++)
                #pragma unroll
                for (int mb = 0; mb < MB; mb++) {
                    uint32_t addr = smem_u32 + 2u * (uint32_t)(
                        st * A_STAGE + (sp * BM + wm0 + mb * 16 + lrow) * KSTRIDE + s16 + lcol);
                    LDSM_X4(Af[sp][mb][0], Af[sp][mb][1], Af[sp][mb][2], Af[sp][mb][3], addr);
                }
            // B split 0: A0*B0 and A1*B0
            uint32_t Bf[NB][2];
            #pragma unroll
            for (int nb2 = 0; nb2 < NB2; nb2++) {
                uint32_t r0, r1, r2, r3;
                uint32_t addr = smem_u32 + 2u * (uint32_t)(
                    B_BASE + st * B_STAGE + (0 * BN + wn0 + nb2 * 16 + lrow) * KSTRIDE + s16 + lcol);
                LDSM_X4(r0, r1, r2, r3, addr);
                Bf[2 * nb2][0] = r0;     Bf[2 * nb2][1] = r2;
                Bf[2 * nb2 + 1][0] = r1; Bf[2 * nb2 + 1][1] = r3;
            }
            #pragma unroll
            for (int mb = 0; mb < MB; mb++)
                #pragma unroll
                for (int nb = 0; nb < NB; nb++) {
                    MMA_16816(acc[mb][nb], Af[0][mb], Bf[nb]);
                    MMA_16816(acc[mb][nb], Af[1][mb], Bf[nb]);
                }
            // B split 1: A0*B1 (reuse Bf registers)
            #pragma unroll
            for (int nb2 = 0; nb2 < NB2; nb2++) {
                uint32_t r0, r1, r2, r3;
                uint32_t addr = smem_u32 + 2u * (uint32_t)(
                    B_BASE + st * B_STAGE + (1 * BN + wn0 + nb2 * 16 + lrow) * KSTRIDE + s16 + lcol);
                LDSM_X4(r0, r1, r2, r3, addr);
                Bf[2 * nb2][0] = r0;     Bf[2 * nb2][1] = r2;
                Bf[2 * nb2 + 1][0] = r1; Bf[2 * nb2 + 1][1] = r3;
            }
            #pragma unroll
            for (int mb = 0; mb < MB; mb++)
                #pragma unroll
                for (int nb = 0; nb < NB; nb++)
                    MMA_16816(acc[mb][nb], Af[0][mb], Bf[nb]);
        }
    }

    // ---------------- epilogue ----------------
    const int lr = lane >> 2;
    const int lc = (lane & 3) * 2;
    #pragma unroll
    for (int mb = 0; mb < MB; mb++) {
        #pragma unroll
        for (int rr2 = 0; rr2 < 2; rr2++) {
            const int rg = row0 + wm0 + mb * 16 + lr + rr2 * 8;
            float ra = 0.f, tm[NC];
            if (MODE != 0) ra = __ldg(&rnA[rg]);
            if (MODE == 2) {
                #pragma unroll
                for (int cc = 0; cc < NC; cc++) tm[cc] = sTm[(rg - row0) * NC + cc];
            }
            #pragma unroll
            for (int nb = 0; nb < NB; nb++) {
                const int cg = col0 + wn0 + nb * 8 + lc;
                float v0 = acc[mb][nb][rr2 * 2];
                float v1 = acc[mb][nb][rr2 * 2 + 1];
                if (MODE != 0) {
                    float rb0 = __ldg(&rnB[cg]);
                    float rb1 = __ldg(&rnB[cg + 1]);
                    float d0 = sqrtf(fmaxf(ra + rb0 - 2.f * v0, 1e-12f));
                    float d1 = sqrtf(fmaxf(ra + rb1 - 2.f * v1, 1e-12f));
                    if (MODE == 2) {
                        float l0 = 0.f, l1 = 0.f;
                        #pragma unroll
                        for (int cc = 0; cc < NC; cc++) {
                            l0 = fmaf(tm[cc], sShl[(cg - col0) * NC + cc], l0);
                            l1 = fmaf(tm[cc], sShl[(cg + 1 - col0) * NC + cc], l1);
                        }
                        d0 += l0; d1 += l1;
                    }
                    v0 = -TEMP * d0; v1 = -TEMP * d1;
                }
                *reinterpret_cast<float2*>(&C[(size_t)rg * N + cg]) = make_float2(v0, v1);
            }
        }
    }
}

// ===================== fused row softmax + split2 (fp16 hi/lo weights) =====================
template<int NCOL, int THREADS>
__global__ void softmax_split_kernel(const float* __restrict__ X,
                                     __half* __restrict__ W0,
                                     __half* __restrict__ W1) {
    constexpr int PER = NCOL / THREADS;
    int row = blockIdx.x;
    const float* xr = X + (size_t)row * NCOL;
    int tid = threadIdx.x;
    float r[PER];
    float mx = -INFINITY;
    #pragma unroll
    for (int i = 0; i < PER; i++) {
        r[i] = xr[tid + i * THREADS];
        mx = fmaxf(mx, r[i]);
    }
    __shared__ float sred[THREADS / 32];
    #pragma unroll
    for (int o = 16; o > 0; o >>= 1) mx = fmaxf(mx, __shfl_xor_sync(0xffffffffu, mx, o));
    if ((tid & 31) == 0) sred[tid >> 5] = mx;
    __syncthreads();
    {
        float m = sred[0];
        #pragma unroll
        for (int i = 1; i < THREADS / 32; i++) m = fmaxf(m, sred[i]);
        mx = m;
    }
    __syncthreads();
    float s = 0.f;
    #pragma unroll
    for (int i = 0; i < PER; i++) {
        r[i] = expf(r[i] - mx);
        s += r[i];
    }
    #pragma unroll
    for (int o = 16; o > 0; o >>= 1) s += __shfl_xor_sync(0xffffffffu, s, o);
    if ((tid & 31) == 0) sred[tid >> 5] = s;
    __syncthreads();
    {
        float m = 0.f;
        #pragma unroll
        for (int i = 0; i < THREADS / 32; i++) m += sred[i];
        s = m;
    }
    float inv = 1.f / s;
    #pragma unroll
    for (int i = 0; i < PER; i++) {
        float wv = r[i] * inv;
        __half h, l;
        split2_one(wv, h, l);
        size_t o = (size_t)row * NCOL + tid + i * THREADS;
        W0[o] = h; W1[o] = l;
    }
}

// ===================== classifier head + x_src split-2 =====================
__global__ void preds_kernel(const float* __restrict__ xsrc, const float* __restrict__ W,
                             const float* __restrict__ b, const float* __restrict__ L,
                             float* __restrict__ t_out, float* __restrict__ xsn,
                             __half* __restrict__ XS0, __half* __restrict__ XS1)
{
    int row = blockIdx.x;
    int tid = threadIdx.x;
    const float* xr = xsrc + (size_t)row * DIM;
    float acc[NC];
    #pragma unroll
    for (int c = 0; c < NC; c++) acc[c] = 0.f;
    float nrm = 0.f;
    for (int k = tid; k < DIM; k += blockDim.x) {
        float xv = xr[k];
        nrm = fmaf(xv, xv, nrm);
        __half h, l;
        split2_one(xv, h, l);
        size_t o = (size_t)row * DIM + k;
        XS0[o] = h; XS1[o] = l;
        #pragma unroll
        for (int c = 0; c < NC; c++) acc[c] = fmaf(xv, __ldg(&W[k * NC + c]), acc[c]);
    }
    __shared__ float red[NC + 1][128];
    #pragma unroll
    for (int c = 0; c < NC; c++) red[c][tid] = acc[c];
    red[NC][tid] = nrm;
    __syncthreads();
    for (int st = 64; st > 0; st >>= 1) {
        if (tid < st) {
            #pragma unroll
            for (int c = 0; c <= NC; c++) red[c][tid] += red[c][tid + st];
        }
        __syncthreads();
    }
    if (tid == 0) {
        float lg[NC], m = -INFINITY, s = 0.f;
        #pragma unroll
        for (int c = 0; c < NC; c++) { lg[c] = red[c][0] + b[c]; m = fmaxf(m, lg[c]); }
        #pragma unroll
        for (int c = 0; c < NC; c++) { lg[c] = expf(lg[c] - m); s += lg[c]; }
        float inv = 1.f / s;
        #pragma unroll
        for (int c = 0; c < NC; c++) {
            float tv = 0.f;
            #pragma unroll
            for (int cc = 0; cc < NC; cc++) tv = fmaf(lg[cc] * inv, L[cc * NC + c], tv);
            t_out[row * NC + c] = tv;
        }
        xsn[row] = red[NC][0];
    }
}

// ===================== fused softmax + (w @ atlT) =====================
__global__ void final_kernel(const float* __restrict__ logits, const float* __restrict__ atlT,
                             float* __restrict__ y)
{
    constexpr int THREADS = 512;
    constexpr int PER = NS / THREADS;   // 16
    int row = blockIdx.x;
    int tid = threadIdx.x;
    const float* xr = logits + (size_t)row * NS;
    float r[PER];
    float mx = -INFINITY;
    #pragma unroll
    for (int i = 0; i < PER; i++) {
        r[i] = xr[tid + i * THREADS];
        mx = fmaxf(mx, r[i]);
    }
    __shared__ float sred[THREADS / 32];
    #pragma unroll
    for (int o = 16; o > 0; o >>= 1) mx = fmaxf(mx, __shfl_xor_sync(0xffffffffu, mx, o));
    if ((tid & 31) == 0) sred[tid >> 5] = mx;
    __syncthreads();
    {
        float m = sred[0];
        #pragma unroll
        for (int i = 1; i < THREADS / 32; i++) m = fmaxf(m, sred[i]);
        mx = m;
    }
    __syncthreads();

    float s = 0.f;
    float e[PER];
    #pragma unroll
    for (int i = 0; i < PER; i++) {
        e[i] = expf(r[i] - mx);
        s += e[i];
    }
    float ya[NC];
    #pragma unroll
    for (int c = 0; c < NC; c++) {
        float a = 0.f;
        #pragma unroll
        for (int i = 0; i < PER; i++)
            a = fmaf(e[i], __ldg(&atlT[(size_t)c * NS + tid + i * THREADS]), a);
        ya[c] = a;
    }
    __shared__ float red[NC + 1][THREADS];
    #pragma unroll
    for (int c = 0; c < NC; c++) red[c][tid] = ya[c];
    red[NC][tid] = s;
    __syncthreads();
    for (int st = THREADS / 2; st > 0; st >>= 1) {
        if (tid < st) {
            #pragma unroll
            for (int c = 0; c <= NC; c++) red[c][tid] += red[c][tid + st];
        }
        __syncthreads();
    }
    if (tid < NC) {
        y[row * NC + tid] = red[tid][0] / red[NC][0];
    }
}

// ===================== launch =====================
extern "C" void kernel_launch(void* const* d_in, const int* in_sizes, int n_in,
                              void* d_out, int out_size)
{
    const float* x   = (const float*)d_in[0];
    const float* tf  = (const float*)d_in[1];
    const float* asf = (const float*)d_in[2];
    const float* sf  = (const float*)d_in[3];
    const float* shl = (const float*)d_in[4];
    const float* atl = (const float*)d_in[5];
    const float* sld = (const float*)d_in[6];
    const float* W   = (const float*)d_in[7];
    const float* b   = (const float*)d_in[8];
    float* y = (float*)d_out;

    float *logits, *xsrc, *tn, *sn, *xn, *xsn, *tbuf, *atlT;
    __half *x2, *tf2, *sf2, *asfT2, *w2, *xs2;
    cudaGetSymbolAddress((void**)&logits, g_logits);
    cudaGetSymbolAddress((void**)&xsrc,   g_xsrc);
    cudaGetSymbolAddress((void**)&tn,     g_tn);
    cudaGetSymbolAddress((void**)&sn,     g_sn);
    cudaGetSymbolAddress((void**)&xn,     g_xn);
    cudaGetSymbolAddress((void**)&xsn,    g_xsn);
    cudaGetSymbolAddress((void**)&tbuf,   g_t);
    cudaGetSymbolAddress((void**)&atlT,   g_atlT);
    cudaGetSymbolAddress((void**)&x2,     g_x2);
    cudaGetSymbolAddress((void**)&tf2,    g_tf2);
    cudaGetSymbolAddress((void**)&sf2,    g_sf2);
    cudaGetSymbolAddress((void**)&asfT2,  g_asfT2);
    cudaGetSymbolAddress((void**)&w2,     g_w2);
    cudaGetSymbolAddress((void**)&xs2,    g_xs2);

    // smem: tiles = 2B * STAGES * 2*(BM+BN) * KSTRIDE; + label region
    const int smem_big = 2 * 3 * 2 * (128 + 256) * KSTRIDE + (128 + 256) * NC * 4;  // 199680
    const int smem_g2  = 2 * 4 * 2 * (64 + 64) * KSTRIDE;                            // 81920
    cudaFuncSetAttribute(mma_gemm_kernel<128, 256, 64, 64, 3, 1>,
                         cudaFuncAttributeMaxDynamicSharedMemorySize, smem_big);
    cudaFuncSetAttribute(mma_gemm_kernel<128, 256, 64, 64, 3, 2>,
                         cudaFuncAttributeMaxDynamicSharedMemorySize, smem_big);
    cudaFuncSetAttribute(mma_gemm_kernel<64, 64, 64, 16, 4, 0>,
                         cudaFuncAttributeMaxDynamicSharedMemorySize, smem_g2);

    const size_t SZ_XD = (size_t)BATCH * DIM;
    const size_t SZ_TD = (size_t)NT * DIM;
    const size_t SZ_SD = (size_t)NS * DIM;
    const size_t SZ_DT = (size_t)DIM * NT;
    const size_t SZ_BN = (size_t)BATCH * NT;

    // 1) fused norm + split-2 (one pass per input) + transposes
    norm_split2_kernel<<<BATCH, 256>>>(x, x2, x2 + SZ_XD, xn);
    norm_split2_kernel<<<NT, 256>>>(tf, tf2, tf2 + SZ_TD, tn);
    norm_split2_kernel<<<NS, 256>>>(sf, sf2, sf2 + SZ_SD, sn);
    split2T_kernel<<<dim3(DIM / 32, NT / 32), 256>>>(asf, asfT2, asfT2 + SZ_DT, NT, DIM);
    atlT_kernel<<<NS / 256, 256>>>(atl, atlT);

    // 2) feature-transport logits: -T * cdist(xf, tf)   [1024 x 8192]
    mma_gemm_kernel<128, 256, 64, 64, 3, 1><<<dim3(NT / 256, BATCH / 128), 256, smem_big>>>(
        x2, x2 + SZ_XD, tf2, tf2 + SZ_TD, logits, NT, DIM, xn, tn, nullptr, nullptr);

    // 3) softmax over Nt, emitting split-2 fp16 weights directly
    softmax_split_kernel<NT, 512><<<BATCH, 512>>>(logits, w2, w2 + SZ_BN);

    // 4) x_src = w_feat @ asf   [1024 x 1024], K = 8192
    mma_gemm_kernel<64, 64, 64, 16, 4, 0><<<dim3(DIM / 64, BATCH / 64), 128, smem_g2>>>(
        w2, w2 + SZ_BN, asfT2, asfT2 + SZ_DT, xsrc, DIM, NT,
        nullptr, nullptr, nullptr, nullptr);

    // 5) classifier head -> tbuf = preds @ L, ||x_src||^2, and x_src split-2
    preds_kernel<<<BATCH, 128>>>(xsrc, W, b, sld, tbuf, xsn, xs2, xs2 + SZ_XD);

    // 6) label-transport logits  [1024 x 8192]
    mma_gemm_kernel<128, 256, 64, 64, 3, 2><<<dim3(NS / 256, BATCH / 128), 256, smem_big>>>(
        xs2, xs2 + SZ_XD, sf2, sf2 + SZ_SD, logits, NS, DIM, xsn, sn, tbuf, shl);

    // 7) softmax over Ns fused with y = w_lab @ atlT
    final_kernel<<<BATCH, 512>>>(logits, atlT, y);
}

// round 12
// speedup vs baseline: 2.2669x; 1.0334x over previous
#include <cuda_runtime.h>
#include <cuda_fp16.h>
#include <math.h>
#include <stdint.h>

// ---------------- problem constants ----------------
#define BATCH 1024
#define NT    8192
#define NS    8192
#define DIM   1024
#define NC    10
#define TEMP  100.0f
#define SPLITK 8

// ---------------- scratch (device globals; no allocation) ----------------
__device__ float g_logits[(size_t)BATCH * NT];   // 32 MB
__device__ float g_xsp[(size_t)SPLITK * BATCH * DIM];  // split-K partials, 32 MB
__device__ float g_tn[NT];
__device__ float g_sn[NS];
__device__ float g_xn[BATCH];
__device__ float g_xsn[BATCH];
__device__ float g_t[BATCH * NC];
__device__ float g_atlT[NC * NS];                // atl transposed [NC, NS]
// fp16 split-2 operand buffers (hi at offset 0, lo at offset SZ)
__device__ __half g_x2  [(size_t)2 * BATCH * DIM];
__device__ __half g_tf2 [(size_t)2 * NT * DIM];
__device__ __half g_sf2 [(size_t)2 * NS * DIM];
__device__ __half g_asfT2[(size_t)2 * DIM * NT];   // asf transposed: [DIM, NT]
__device__ __half g_w2  [(size_t)2 * BATCH * NT];
__device__ __half g_xs2 [(size_t)2 * BATCH * DIM];

// ===================== asm helpers (sm_80-era PTX; compiles for compute_103) =====================
__device__ __forceinline__ uint32_t smem_to_u32(const void* smem_ptr) {
    uint32_t addr;
    asm("{ .reg .u64 tmp; cvta.to.shared.u64 tmp, %1; cvt.u32.u64 %0, tmp; }"
        : "=r"(addr) : "l"(smem_ptr));
    return addr;
}
#define CP_ASYNC_CG16(dst, src) \
    asm volatile("cp.async.cg.shared.global [%0], [%1], 16;" :: "r"(dst), "l"(src))
#define CP_COMMIT() asm volatile("cp.async.commit_group;" ::: "memory")
#define CP_WAIT(n)  asm volatile("cp.async.wait_group %0;" :: "n"(n) : "memory")
#define LDSM_X4(r0, r1, r2, r3, addr) \
    asm volatile("ldmatrix.sync.aligned.m8n8.x4.shared.b16 {%0,%1,%2,%3}, [%4];" \
        : "=r"(r0), "=r"(r1), "=r"(r2), "=r"(r3) : "r"(addr))
#define MMA_16816(d, a, b) \
    asm volatile("mma.sync.aligned.m16n8k16.row.col.f32.f16.f16.f32 " \
        "{%0,%1,%2,%3}, {%4,%5,%6,%7}, {%8,%9}, {%0,%1,%2,%3};" \
        : "+f"((d)[0]), "+f"((d)[1]), "+f"((d)[2]), "+f"((d)[3]) \
        : "r"((a)[0]), "r"((a)[1]), "r"((a)[2]), "r"((a)[3]), \
          "r"((b)[0]), "r"((b)[1]))

// ===================== fp16 split-2 =====================
__device__ __forceinline__ void split2_one(float x, __half& h0, __half& h1) {
    h0 = __float2half_rn(x);
    h1 = __float2half_rn(x - __half2float(h0));
}

// fused: row squared-norm + split-2 (one pass over X). X: [R, 1024]; 256 thr/row.
__global__ void norm_split2_kernel(const float* __restrict__ X,
                                   __half* __restrict__ O0,
                                   __half* __restrict__ O1,
                                   float* __restrict__ norms) {
    int row = blockIdx.x;
    int tid = threadIdx.x;
    const float* xr = X + (size_t)row * DIM;
    float4 v = *reinterpret_cast<const float4*>(xr + tid * 4);
    float s = v.x * v.x + v.y * v.y + v.z * v.z + v.w * v.w;
    __half a0, a1, b0, b1, c0, c1, d0, d1;
    split2_one(v.x, a0, a1);
    split2_one(v.y, b0, b1);
    split2_one(v.z, c0, c1);
    split2_one(v.w, d0, d1);
    size_t o = (size_t)row * DIM + tid * 4;
    *reinterpret_cast<__half2*>(O0 + o)     = __halves2half2(a0, b0);
    *reinterpret_cast<__half2*>(O0 + o + 2) = __halves2half2(c0, d0);
    *reinterpret_cast<__half2*>(O1 + o)     = __halves2half2(a1, b1);
    *reinterpret_cast<__half2*>(O1 + o + 2) = __halves2half2(c1, d1);
    #pragma unroll
    for (int off = 16; off > 0; off >>= 1) s += __shfl_xor_sync(0xffffffffu, s, off);
    __shared__ float ws[8];
    if ((tid & 31) == 0) ws[tid >> 5] = s;
    __syncthreads();
    if (tid == 0) {
        float t = 0.f;
        #pragma unroll
        for (int i = 0; i < 8; i++) t += ws[i];
        norms[row] = t;
    }
}

// transpose + split2: X [R, Cc] fp32 -> O* [Cc, R] fp16.  32x32 tiles, 256 threads.
__global__ void split2T_kernel(const float* __restrict__ X,
                               __half* __restrict__ O0,
                               __half* __restrict__ O1, int R, int Cc) {
    __shared__ float t[32][33];
    int tx = threadIdx.x & 31;
    int ty = threadIdx.x >> 5;
    int r0 = blockIdx.y * 32;
    int c0 = blockIdx.x * 32;
    #pragma unroll
    for (int yy = 0; yy < 4; yy++) {
        int r = ty * 4 + yy;
        t[r][tx] = X[(size_t)(r0 + r) * Cc + c0 + tx];
    }
    __syncthreads();
    int p = tx & 15;
    int half = tx >> 4;
    #pragma unroll
    for (int yy = 0; yy < 2; yy++) {
        int j = ty * 2 + half + yy * 16;
        float v0 = t[p * 2][j], v1 = t[p * 2 + 1][j];
        __half h0, l0, h1, l1;
        split2_one(v0, h0, l0);
        split2_one(v1, h1, l1);
        size_t o = (size_t)(c0 + j) * R + r0 + p * 2;
        *reinterpret_cast<__half2*>(O0 + o) = __halves2half2(h0, h1);
        *reinterpret_cast<__half2*>(O1 + o) = __halves2half2(l0, l1);
    }
}

// tiny: atl [NS, NC] -> atlT [NC, NS]
__global__ void atlT_kernel(const float* __restrict__ atl, float* __restrict__ atlT) {
    int j = blockIdx.x * blockDim.x + threadIdx.x;
    if (j >= NS) return;
    #pragma unroll
    for (int c = 0; c < NC; c++) atlT[(size_t)c * NS + j] = atl[(size_t)j * NC + c];
}

// ===================== mma.sync fp16 split-2 GEMM (split-K capable) =====================
// acc = A0*B0 + A0*B1 + A1*B0   (A = A0 + A1, B = B0 + B1; drop A1*B1)
// MODE 0: C = acc;  MODE 1: C = -T*sqrt(...);  MODE 2: MODE1 + label cost
// blockIdx.z selects K-slice [z*klen, (z+1)*klen); output goes to C + z*czstride.
#define KSTRIDE 40   // 32 used + 8 pad (fp16 elems) -> conflict-free ldmatrix

template<int BM, int BN, int THREADS, int STAGES>
__device__ __forceinline__ void load_stage_fn(
    const __half* __restrict__ A0g, const __half* __restrict__ A1g,
    const __half* __restrict__ B0g, const __half* __restrict__ B1g,
    uint32_t smem_u32, int st, int k0, int row0, int col0, int K, int tid)
{
    constexpr int A_STAGE = 2 * BM * KSTRIDE;
    constexpr int B_STAGE = 2 * BN * KSTRIDE;
    constexpr int B_BASE  = STAGES * A_STAGE;
    constexpr int TOT_A = BM * 8;
    constexpr int CPT = (BM + BN) * 8 / THREADS;
    #pragma unroll
    for (int t = 0; t < CPT; t++) {
        int i = tid + t * THREADS;
        if (i < TOT_A) {
            int sp = i / (BM * 4);
            int rr = (i >> 2) % BM;
            int kc = i & 3;
            const __half* g = sp ? A1g : A0g;
            const __half* src = g + (size_t)(row0 + rr) * K + k0 + kc * 8;
            uint32_t dst = smem_u32 + 2u * (uint32_t)(
                st * A_STAGE + (sp * BM + rr) * KSTRIDE + kc * 8);
            CP_ASYNC_CG16(dst, src);
        } else {
            int j = i - TOT_A;
            int sp = j / (BN * 4);
            int rr = (j >> 2) % BN;
            int kc = j & 3;
            const __half* g = sp ? B1g : B0g;
            const __half* src = g + (size_t)(col0 + rr) * K + k0 + kc * 8;
            uint32_t dst = smem_u32 + 2u * (uint32_t)(
                B_BASE + st * B_STAGE + (sp * BN + rr) * KSTRIDE + kc * 8);
            CP_ASYNC_CG16(dst, src);
        }
    }
}

template<int BM, int BN, int WM, int WN, int STAGES, int MODE>
__global__ void __launch_bounds__((BM / WM) * (BN / WN) * 32, 1)
mma_gemm_kernel(const __half* __restrict__ A0g, const __half* __restrict__ A1g,
                const __half* __restrict__ B0g, const __half* __restrict__ B1g,
                float* __restrict__ C, int N, int K, int klen, size_t czstride,
                const float* __restrict__ rnA, const float* __restrict__ rnB,
                const float* __restrict__ Tm, const float* __restrict__ SHL)
{
    constexpr int THREADS = (BM / WM) * (BN / WN) * 32;
    constexpr int MB = WM / 16;
    constexpr int NB = WN / 8;
    constexpr int NB2 = WN / 16;
    constexpr int A_STAGE = 2 * BM * KSTRIDE;
    constexpr int B_STAGE = 2 * BN * KSTRIDE;
    constexpr int B_BASE  = STAGES * A_STAGE;
    constexpr int TILE_ELEMS = STAGES * (A_STAGE + B_STAGE);

    extern __shared__ char smem[];
    const uint32_t smem_u32 = smem_to_u32(smem);
    const int tid = threadIdx.x;
    const int wid = tid >> 5;
    const int lane = tid & 31;
    const int warps_n = BN / WN;
    const int wm0 = (wid / warps_n) * WM;
    const int wn0 = (wid % warps_n) * WN;
    const int row0 = blockIdx.y * BM;
    const int col0 = blockIdx.x * BN;
    const int kbase = blockIdx.z * klen;
    float* Cz = C + (size_t)blockIdx.z * czstride;

    float* sTm  = reinterpret_cast<float*>(smem + 2 * TILE_ELEMS);
    float* sShl = sTm + BM * NC;
    if (MODE == 2) {
        for (int i = tid; i < BM * NC; i += THREADS)
            sTm[i] = __ldg(&Tm[(size_t)(row0 + i / NC) * NC + (i % NC)]);
        for (int i = tid; i < BN * NC; i += THREADS)
            sShl[i] = __ldg(&SHL[(size_t)(col0 + i / NC) * NC + (i % NC)]);
    }

    float acc[MB][NB][4];
    #pragma unroll
    for (int i = 0; i < MB; i++)
        #pragma unroll
        for (int j = 0; j < NB; j++)
            #pragma unroll
            for (int q = 0; q < 4; q++) acc[i][j][q] = 0.f;

    const int nch = klen >> 5;   // BK = 32
    #pragma unroll
    for (int s = 0; s < STAGES - 1; s++) {
        load_stage_fn<BM, BN, THREADS, STAGES>(A0g, A1g, B0g, B1g, smem_u32,
                                               s, kbase + (s << 5), row0, col0, K, tid);
        CP_COMMIT();
    }

    const int lrow = lane & 15;
    const int lcol = (lane >> 4) << 3;

    for (int c = 0; c < nch; c++) {
        CP_WAIT(STAGES - 2);
        __syncthreads();
        int pf = c + STAGES - 1;
        if (pf < nch)
            load_stage_fn<BM, BN, THREADS, STAGES>(A0g, A1g, B0g, B1g, smem_u32,
                                                   pf % STAGES, kbase + (pf << 5),
                                                   row0, col0, K, tid);
        CP_COMMIT();
        const int st = c % STAGES;

        #pragma unroll
        for (int s16 = 0; s16 < 32; s16 += 16) {
            uint32_t Af[2][MB][4];
            #pragma unroll
            for (int sp = 0; sp < 2; sp++)
                #pragma unroll
                for (int mb = 0; mb < MB; mb++) {
                    uint32_t addr = smem_u32 + 2u * (uint32_t)(
                        st * A_STAGE + (sp * BM + wm0 + mb * 16 + lrow) * KSTRIDE + s16 + lcol);
                    LDSM_X4(Af[sp][mb][0], Af[sp][mb][1], Af[sp][mb][2], Af[sp][mb][3], addr);
                }
            uint32_t Bf[NB][2];
            #pragma unroll
            for (int nb2 = 0; nb2 < NB2; nb2++) {
                uint32_t r0, r1, r2, r3;
                uint32_t addr = smem_u32 + 2u * (uint32_t)(
                    B_BASE + st * B_STAGE + (0 * BN + wn0 + nb2 * 16 + lrow) * KSTRIDE + s16 + lcol);
                LDSM_X4(r0, r1, r2, r3, addr);
                Bf[2 * nb2][0] = r0;     Bf[2 * nb2][1] = r2;
                Bf[2 * nb2 + 1][0] = r1; Bf[2 * nb2 + 1][1] = r3;
            }
            #pragma unroll
            for (int mb = 0; mb < MB; mb++)
                #pragma unroll
                for (int nb = 0; nb < NB; nb++) {
                    MMA_16816(acc[mb][nb], Af[0][mb], Bf[nb]);
                    MMA_16816(acc[mb][nb], Af[1][mb], Bf[nb]);
                }
            #pragma unroll
            for (int nb2 = 0; nb2 < NB2; nb2++) {
                uint32_t r0, r1, r2, r3;
                uint32_t addr = smem_u32 + 2u * (uint32_t)(
                    B_BASE + st * B_STAGE + (1 * BN + wn0 + nb2 * 16 + lrow) * KSTRIDE + s16 + lcol);
                LDSM_X4(r0, r1, r2, r3, addr);
                Bf[2 * nb2][0] = r0;     Bf[2 * nb2][1] = r2;
                Bf[2 * nb2 + 1][0] = r1; Bf[2 * nb2 + 1][1] = r3;
            }
            #pragma unroll
            for (int mb = 0; mb < MB; mb++)
                #pragma unroll
                for (int nb = 0; nb < NB; nb++)
                    MMA_16816(acc[mb][nb], Af[0][mb], Bf[nb]);
        }
    }

    // ---------------- epilogue ----------------
    const int lr = lane >> 2;
    const int lc = (lane & 3) * 2;
    #pragma unroll
    for (int mb = 0; mb < MB; mb++) {
        #pragma unroll
        for (int rr2 = 0; rr2 < 2; rr2++) {
            const int rg = row0 + wm0 + mb * 16 + lr + rr2 * 8;
            float ra = 0.f, tm[NC];
            if (MODE != 0) ra = __ldg(&rnA[rg]);
            if (MODE == 2) {
                #pragma unroll
                for (int cc = 0; cc < NC; cc++) tm[cc] = sTm[(rg - row0) * NC + cc];
            }
            #pragma unroll
            for (int nb = 0; nb < NB; nb++) {
                const int cg = col0 + wn0 + nb * 8 + lc;
                float v0 = acc[mb][nb][rr2 * 2];
                float v1 = acc[mb][nb][rr2 * 2 + 1];
                if (MODE != 0) {
                    float rb0 = __ldg(&rnB[cg]);
                    float rb1 = __ldg(&rnB[cg + 1]);
                    float d0 = sqrtf(fmaxf(ra + rb0 - 2.f * v0, 1e-12f));
                    float d1 = sqrtf(fmaxf(ra + rb1 - 2.f * v1, 1e-12f));
                    if (MODE == 2) {
                        float l0 = 0.f, l1 = 0.f;
                        #pragma unroll
                        for (int cc = 0; cc < NC; cc++) {
                            l0 = fmaf(tm[cc], sShl[(cg - col0) * NC + cc], l0);
                            l1 = fmaf(tm[cc], sShl[(cg + 1 - col0) * NC + cc], l1);
                        }
                        d0 += l0; d1 += l1;
                    }
                    v0 = -TEMP * d0; v1 = -TEMP * d1;
                }
                *reinterpret_cast<float2*>(&Cz[(size_t)rg * N + cg]) = make_float2(v0, v1);
            }
        }
    }
}

// ===================== fused row softmax + split2 (fp16 hi/lo weights) =====================
template<int NCOL, int THREADS>
__global__ void softmax_split_kernel(const float* __restrict__ X,
                                     __half* __restrict__ W0,
                                     __half* __restrict__ W1) {
    constexpr int PER = NCOL / THREADS;
    int row = blockIdx.x;
    const float* xr = X + (size_t)row * NCOL;
    int tid = threadIdx.x;
    float r[PER];
    float mx = -INFINITY;
    #pragma unroll
    for (int i = 0; i < PER; i++) {
        r[i] = xr[tid + i * THREADS];
        mx = fmaxf(mx, r[i]);
    }
    __shared__ float sred[THREADS / 32];
    #pragma unroll
    for (int o = 16; o > 0; o >>= 1) mx = fmaxf(mx, __shfl_xor_sync(0xffffffffu, mx, o));
    if ((tid & 31) == 0) sred[tid >> 5] = mx;
    __syncthreads();
    {
        float m = sred[0];
        #pragma unroll
        for (int i = 1; i < THREADS / 32; i++) m = fmaxf(m, sred[i]);
        mx = m;
    }
    __syncthreads();
    float s = 0.f;
    #pragma unroll
    for (int i = 0; i < PER; i++) {
        r[i] = expf(r[i] - mx);
        s += r[i];
    }
    #pragma unroll
    for (int o = 16; o > 0; o >>= 1) s += __shfl_xor_sync(0xffffffffu, s, o);
    if ((tid & 31) == 0) sred[tid >> 5] = s;
    __syncthreads();
    {
        float m = 0.f;
        #pragma unroll
        for (int i = 0; i < THREADS / 32; i++) m += sred[i];
        s = m;
    }
    float inv = 1.f / s;
    #pragma unroll
    for (int i = 0; i < PER; i++) {
        float wv = r[i] * inv;
        __half h, l;
        split2_one(wv, h, l);
        size_t o = (size_t)row * NCOL + tid + i * THREADS;
        W0[o] = h; W1[o] = l;
    }
}

// ===================== classifier head + split-K reduce + x_src split-2 =====================
__global__ void preds_kernel(const float* __restrict__ xsp, const float* __restrict__ W,
                             const float* __restrict__ b, const float* __restrict__ L,
                             float* __restrict__ t_out, float* __restrict__ xsn,
                             __half* __restrict__ XS0, __half* __restrict__ XS1)
{
    int row = blockIdx.x;
    int tid = threadIdx.x;
    float acc[NC];
    #pragma unroll
    for (int c = 0; c < NC; c++) acc[c] = 0.f;
    float nrm = 0.f;
    for (int k = tid; k < DIM; k += blockDim.x) {
        size_t o = (size_t)row * DIM + k;
        float xv = 0.f;
        #pragma unroll
        for (int z = 0; z < SPLITK; z++)
            xv += xsp[(size_t)z * BATCH * DIM + o];
        nrm = fmaf(xv, xv, nrm);
        __half h, l;
        split2_one(xv, h, l);
        XS0[o] = h; XS1[o] = l;
        #pragma unroll
        for (int c = 0; c < NC; c++) acc[c] = fmaf(xv, __ldg(&W[k * NC + c]), acc[c]);
    }
    __shared__ float red[NC + 1][128];
    #pragma unroll
    for (int c = 0; c < NC; c++) red[c][tid] = acc[c];
    red[NC][tid] = nrm;
    __syncthreads();
    for (int st = 64; st > 0; st >>= 1) {
        if (tid < st) {
            #pragma unroll
            for (int c = 0; c <= NC; c++) red[c][tid] += red[c][tid + st];
        }
        __syncthreads();
    }
    if (tid == 0) {
        float lg[NC], m = -INFINITY, s = 0.f;
        #pragma unroll
        for (int c = 0; c < NC; c++) { lg[c] = red[c][0] + b[c]; m = fmaxf(m, lg[c]); }
        #pragma unroll
        for (int c = 0; c < NC; c++) { lg[c] = expf(lg[c] - m); s += lg[c]; }
        float inv = 1.f / s;
        #pragma unroll
        for (int c = 0; c < NC; c++) {
            float tv = 0.f;
            #pragma unroll
            for (int cc = 0; cc < NC; cc++) tv = fmaf(lg[cc] * inv, L[cc * NC + c], tv);
            t_out[row * NC + c] = tv;
        }
        xsn[row] = red[NC][0];
    }
}

// ===================== fused softmax + (w @ atlT) =====================
__global__ void final_kernel(const float* __restrict__ logits, const float* __restrict__ atlT,
                             float* __restrict__ y)
{
    constexpr int THREADS = 512;
    constexpr int PER = NS / THREADS;   // 16
    int row = blockIdx.x;
    int tid = threadIdx.x;
    const float* xr = logits + (size_t)row * NS;
    float r[PER];
    float mx = -INFINITY;
    #pragma unroll
    for (int i = 0; i < PER; i++) {
        r[i] = xr[tid + i * THREADS];
        mx = fmaxf(mx, r[i]);
    }
    __shared__ float sred[THREADS / 32];
    #pragma unroll
    for (int o = 16; o > 0; o >>= 1) mx = fmaxf(mx, __shfl_xor_sync(0xffffffffu, mx, o));
    if ((tid & 31) == 0) sred[tid >> 5] = mx;
    __syncthreads();
    {
        float m = sred[0];
        #pragma unroll
        for (int i = 1; i < THREADS / 32; i++) m = fmaxf(m, sred[i]);
        mx = m;
    }
    __syncthreads();

    float s = 0.f;
    float e[PER];
    #pragma unroll
    for (int i = 0; i < PER; i++) {
        e[i] = expf(r[i] - mx);
        s += e[i];
    }
    float ya[NC];
    #pragma unroll
    for (int c = 0; c < NC; c++) {
        float a = 0.f;
        #pragma unroll
        for (int i = 0; i < PER; i++)
            a = fmaf(e[i], __ldg(&atlT[(size_t)c * NS + tid + i * THREADS]), a);
        ya[c] = a;
    }
    __shared__ float red[NC + 1][THREADS];
    #pragma unroll
    for (int c = 0; c < NC; c++) red[c][tid] = ya[c];
    red[NC][tid] = s;
    __syncthreads();
    for (int st = THREADS / 2; st > 0; st >>= 1) {
        if (tid < st) {
            #pragma unroll
            for (int c = 0; c <= NC; c++) red[c][tid] += red[c][tid + st];
        }
        __syncthreads();
    }
    if (tid < NC) {
        y[row * NC + tid] = red[tid][0] / red[NC][0];
    }
}

// ===================== launch =====================
extern "C" void kernel_launch(void* const* d_in, const int* in_sizes, int n_in,
                              void* d_out, int out_size)
{
    const float* x   = (const float*)d_in[0];
    const float* tf  = (const float*)d_in[1];
    const float* asf = (const float*)d_in[2];
    const float* sf  = (const float*)d_in[3];
    const float* shl = (const float*)d_in[4];
    const float* atl = (const float*)d_in[5];
    const float* sld = (const float*)d_in[6];
    const float* W   = (const float*)d_in[7];
    const float* b   = (const float*)d_in[8];
    float* y = (float*)d_out;

    float *logits, *xsp, *tn, *sn, *xn, *xsn, *tbuf, *atlT;
    __half *x2, *tf2, *sf2, *asfT2, *w2, *xs2;
    cudaGetSymbolAddress((void**)&logits, g_logits);
    cudaGetSymbolAddress((void**)&xsp,    g_xsp);
    cudaGetSymbolAddress((void**)&tn,     g_tn);
    cudaGetSymbolAddress((void**)&sn,     g_sn);
    cudaGetSymbolAddress((void**)&xn,     g_xn);
    cudaGetSymbolAddress((void**)&xsn,    g_xsn);
    cudaGetSymbolAddress((void**)&tbuf,   g_t);
    cudaGetSymbolAddress((void**)&atlT,   g_atlT);
    cudaGetSymbolAddress((void**)&x2,     g_x2);
    cudaGetSymbolAddress((void**)&tf2,    g_tf2);
    cudaGetSymbolAddress((void**)&sf2,    g_sf2);
    cudaGetSymbolAddress((void**)&asfT2,  g_asfT2);
    cudaGetSymbolAddress((void**)&w2,     g_w2);
    cudaGetSymbolAddress((void**)&xs2,    g_xs2);

    // smem: tiles = 2B * STAGES * 2*(BM+BN) * KSTRIDE; + label region
    const int smem_big = 2 * 3 * 2 * (128 + 256) * KSTRIDE + (128 + 256) * NC * 4;  // 199680
    const int smem_g2  = 2 * 3 * 2 * (128 + 128) * KSTRIDE;                          // 122880
    cudaFuncSetAttribute(mma_gemm_kernel<128, 256, 64, 64, 3, 1>,
                         cudaFuncAttributeMaxDynamicSharedMemorySize, smem_big);
    cudaFuncSetAttribute(mma_gemm_kernel<128, 256, 64, 64, 3, 2>,
                         cudaFuncAttributeMaxDynamicSharedMemorySize, smem_big);
    cudaFuncSetAttribute(mma_gemm_kernel<128, 128, 64, 32, 3, 0>,
                         cudaFuncAttributeMaxDynamicSharedMemorySize, smem_g2);

    const size_t SZ_XD = (size_t)BATCH * DIM;
    const size_t SZ_TD = (size_t)NT * DIM;
    const size_t SZ_SD = (size_t)NS * DIM;
    const size_t SZ_DT = (size_t)DIM * NT;
    const size_t SZ_BN = (size_t)BATCH * NT;

    // 1) fused norm + split-2 (one pass per input) + transposes
    norm_split2_kernel<<<BATCH, 256>>>(x, x2, x2 + SZ_XD, xn);
    norm_split2_kernel<<<NT, 256>>>(tf, tf2, tf2 + SZ_TD, tn);
    norm_split2_kernel<<<NS, 256>>>(sf, sf2, sf2 + SZ_SD, sn);
    split2T_kernel<<<dim3(DIM / 32, NT / 32), 256>>>(asf, asfT2, asfT2 + SZ_DT, NT, DIM);
    atlT_kernel<<<NS / 256, 256>>>(atl, atlT);

    // 2) feature-transport logits: -T * cdist(xf, tf)   [1024 x 8192]
    mma_gemm_kernel<128, 256, 64, 64, 3, 1><<<dim3(NT / 256, BATCH / 128), 256, smem_big>>>(
        x2, x2 + SZ_XD, tf2, tf2 + SZ_TD, logits, NT, DIM, DIM, 0,
        xn, tn, nullptr, nullptr);

    // 3) softmax over Nt, emitting split-2 fp16 weights directly
    softmax_split_kernel<NT, 512><<<BATCH, 512>>>(logits, w2, w2 + SZ_BN);

    // 4) x_src partials = w_feat @ asf   [1024 x 1024], K = 8192, split-K = 8
    mma_gemm_kernel<128, 128, 64, 32, 3, 0>
        <<<dim3(DIM / 128, BATCH / 128, SPLITK), 256, smem_g2>>>(
        w2, w2 + SZ_BN, asfT2, asfT2 + SZ_DT, xsp, DIM, NT, NT / SPLITK, SZ_XD,
        nullptr, nullptr, nullptr, nullptr);

    // 5) classifier head: reduce split-K partials -> preds@L, ||x_src||^2, x_src split-2
    preds_kernel<<<BATCH, 128>>>(xsp, W, b, sld, tbuf, xsn, xs2, xs2 + SZ_XD);

    // 6) label-transport logits  [1024 x 8192]
    mma_gemm_kernel<128, 256, 64, 64, 3, 2><<<dim3(NS / 256, BATCH / 128), 256, smem_big>>>(
        xs2, xs2 + SZ_XD, sf2, sf2 + SZ_SD, logits, NS, DIM, DIM, 0,
        xsn, sn, tbuf, shl);

    // 7) softmax over Ns fused with y = w_lab @ atlT
    final_kernel<<<BATCH, 512>>>(logits, atlT, y);
}